// round 15
// baseline (speedup 1.0000x reference)
#include <cuda_runtime.h>
#include <cuda_bf16.h>
#include <cstdint>

#define TT 2048
#define BT 16384
#define DD 512
#define KK 1024
#define HALF_N 8388608u   // BT*KK/2

// ---------------- scratch (static device allocations only) ----------------
__device__ __nv_bfloat16 g_h1h[BT * 256];   // conv1 / dec1 output, bf16 hi
__device__ __nv_bfloat16 g_h1l[BT * 256];   // bf16 lo
__device__ __nv_bfloat16 g_zh[BT * DD];     // encoder z, bf16 hi
__device__ __nv_bfloat16 g_zl[BT * DD];     // bf16 lo
__device__ __nv_bfloat16 g_cbh[KK * DD];    // codebook bf16 hi
__device__ __nv_bfloat16 g_cbl[KK * DD];    // bf16 lo
__device__ float g_rn2[BT];                 // ||z||^2 per row
__device__ float g_cbT[DD * KK];            // codebook transposed [d][k]
__device__ float g_dist[BT * KK];           // dot products <z, c_k>  (64MB)
__device__ float g_G[KK * KK];              // Gram matrix cb·cbT     (4MB)
__device__ float g_csq[KK];                 // = diag(G)
__device__ float g_wT[1048576];             // [tap][ci][co] fp32 weights (4MB)
__device__ __nv_bfloat16 g_wtth[491520];    // [tap][co][ci] bf16 hi
__device__ __nv_bfloat16 g_wttl[491520];    // bf16 lo
__device__ float g_U[3 * KK * 256];         // U[tap][k][co] = cb·W1_tap^T (3MB)
__device__ int   g_sel[BT * 8];
__device__ unsigned g_fk[16];
__device__ float g_window;
__device__ float g_acc[2];   // [0]=commit sum, [1]=mse sum

#define WT_O1 0
#define WT_O2 86016
#define WT_O3 479232
#define WT_O4 872448
#define WT_END 970752
#define WTT_O2 0
#define WTT_O4 393216
#define WTT_END 491520

// ---------------- packed f32x2 helpers ----------------
__device__ __forceinline__ void splat2(unsigned long long& d, float a) {
    asm("mov.b64 %0, {%1, %1};" : "=l"(d) : "f"(a));
}
__device__ __forceinline__ void pack2(unsigned long long& d, float a, float b) {
    asm("mov.b64 %0, {%1, %2};" : "=l"(d) : "f"(a), "f"(b));
}
__device__ __forceinline__ void unpack2(float& a, float& b, unsigned long long d) {
    asm("mov.b64 {%0, %1}, %2;" : "=f"(a), "=f"(b) : "l"(d));
}
__device__ __forceinline__ void ffma2(unsigned long long& acc,
                                      unsigned long long a, unsigned long long b) {
    asm("fma.rn.f32x2 %0, %1, %2, %0;" : "+l"(acc) : "l"(a), "l"(b));
}

// ---------------- mma.sync / ldmatrix helpers ----------------
__device__ __forceinline__ uint32_t smem_u32(const void* p) {
    uint32_t a;
    asm("{ .reg .u64 t; cvta.to.shared.u64 t, %1; cvt.u32.u64 %0, t; }"
        : "=r"(a) : "l"(p));
    return a;
}
#define LDSM_X4(r0, r1, r2, r3, addr) \
    asm volatile("ldmatrix.sync.aligned.m8n8.x4.shared.b16 {%0,%1,%2,%3}, [%4];" \
        : "=r"(r0), "=r"(r1), "=r"(r2), "=r"(r3) : "r"(addr))
#define MMA_BF16(d, a, b0, b1) \
    asm volatile("mma.sync.aligned.m16n8k16.row.col.f32.bf16.bf16.f32 " \
        "{%0,%1,%2,%3}, {%4,%5,%6,%7}, {%8,%9}, {%0,%1,%2,%3};" \
        : "+f"((d)[0]), "+f"((d)[1]), "+f"((d)[2]), "+f"((d)[3]) \
        : "r"((a)[0]), "r"((a)[1]), "r"((a)[2]), "r"((a)[3]), "r"(b0), "r"(b1))

// ---------------- JAX threefry2x32 (exact) ----------------
__host__ __device__ inline void tf2x32(unsigned k0, unsigned k1,
                                       unsigned x0, unsigned x1,
                                       unsigned& o0, unsigned& o1) {
    unsigned ks2 = k0 ^ k1 ^ 0x1BD11BDAu;
    x0 += k0; x1 += k1;
#define TF_RND(r) { x0 += x1; x1 = (x1 << (r)) | (x1 >> (32 - (r))); x1 ^= x0; }
    TF_RND(13) TF_RND(15) TF_RND(26) TF_RND(6)
    x0 += k1;  x1 += ks2 + 1u;
    TF_RND(17) TF_RND(29) TF_RND(16) TF_RND(24)
    x0 += ks2; x1 += k0 + 2u;
    TF_RND(13) TF_RND(15) TF_RND(26) TF_RND(6)
    x0 += k0;  x1 += k1 + 3u;
    TF_RND(17) TF_RND(29) TF_RND(16) TF_RND(24)
    x0 += k1;  x1 += ks2 + 4u;
    TF_RND(13) TF_RND(15) TF_RND(26) TF_RND(6)
    x0 += ks2; x1 += k0 + 5u;
#undef TF_RND
    o0 = x0; o1 = x1;
}

__device__ inline float gumbel_from_bits(unsigned bits) {
    float f = __uint_as_float((bits >> 9) | 0x3f800000u) - 1.0f;
    float u = (f == 0.0f) ? 1.17549435e-38f : f;
    return -__logf(-__logf(u));
}

__device__ inline unsigned fmap(float f) {
    unsigned u = __float_as_uint(f);
    return (u & 0x80000000u) ? ~u : (u | 0x80000000u);
}
__device__ inline float unfmap(unsigned u) {
    unsigned v = (u & 0x80000000u) ? (u ^ 0x80000000u) : ~u;
    return __uint_as_float(v);
}

__device__ inline float gelu_exact(float v) {
    return 0.5f * v * (1.0f + erff(v * 0.7071067811865476f));
}

__device__ __forceinline__ void bsplit(float v, __nv_bfloat16& h, __nv_bfloat16& l) {
    h = __float2bfloat16(v);
    l = __float2bfloat16(v - __bfloat162float(h));
}

// ---------------- codebook transpose + split ----------------
__global__ void transpose_cb(const float* __restrict__ cb) {
    __shared__ float t[32][33];
    int k0 = blockIdx.x * 32;
    int d0 = blockIdx.y * 32;
    int tx = threadIdx.x, ty = threadIdx.y;  // 32 x 8
    for (int l = 0; l < 32; l += 8)
        t[ty + l][tx] = cb[(k0 + ty + l) * DD + d0 + tx];
    __syncthreads();
    for (int l = 0; l < 32; l += 8)
        g_cbT[(d0 + ty + l) * KK + k0 + tx] = t[tx][ty + l];
}

__global__ void cb_split(const float* __restrict__ cb) {
    int i = blockIdx.x * 256 + threadIdx.x;   // KK*DD total
    float v = cb[i];
    __nv_bfloat16 h, l;
    bsplit(v, h, l);
    g_cbh[i] = h;
    g_cbl[i] = l;
}

// ---------------- merged weight transpose (fp32 + split bf16) --------------
__device__ __forceinline__ void wt_range(int local, const float* __restrict__ w,
                                         int CIN, int COUT, int CIN16, int PAD,
                                         float* __restrict__ dst) {
    int co = local % PAD;
    int rest = local / PAD;
    int ci = rest % CIN16;
    int tap = rest / CIN16;
    float v = 0.0f;
    if (ci < CIN && co < COUT)
        v = w[((size_t)co * CIN + ci) * 3 + tap];
    dst[local] = v;
}
__device__ __forceinline__ void wtt_range(int local, const float* __restrict__ w,
                                          int CIN, int COUT, int ROWS,
                                          __nv_bfloat16* __restrict__ dh,
                                          __nv_bfloat16* __restrict__ dl) {
    int ci = local % CIN;
    int rest = local / CIN;
    int co = rest % ROWS;
    int tap = rest / ROWS;
    float v = 0.0f;
    if (co < COUT)
        v = w[((size_t)co * CIN + ci) * 3 + tap];
    __nv_bfloat16 h, l;
    bsplit(v, h, l);
    dh[local] = h;
    dl[local] = l;
}
__global__ void transpose_w_all(const float* __restrict__ w1, const float* __restrict__ w2,
                                const float* __restrict__ w3, const float* __restrict__ w4) {
    int idx = blockIdx.x * 256 + threadIdx.x;
    if (idx < BT) g_rn2[idx] = 0.0f;
    if (idx < WT_END) {
        if (idx < WT_O2)      wt_range(idx - WT_O1, w1, 100, 256, 112, 256, g_wT + WT_O1);
        else if (idx < WT_O3) wt_range(idx - WT_O2, w2, 256, 512, 256, 512, g_wT + WT_O2);
        else if (idx < WT_O4) wt_range(idx - WT_O3, w3, 512, 256, 512, 256, g_wT + WT_O3);
        else                  wt_range(idx - WT_O4, w4, 256, 100, 256, 128, g_wT + WT_O4);
    } else {
        int j = idx - WT_END;
        if (j >= WTT_END) return;
        if (j < WTT_O4) wtt_range(j - WTT_O2, w2, 256, 512, 512,
                                  g_wtth + WTT_O2, g_wttl + WTT_O2);
        else            wtt_range(j - WTT_O4, w4, 256, 100, 128,
                                  g_wtth + WTT_O4, g_wttl + WTT_O4);
    }
}

// ---------------- conv1: FFMA2 conv (CIN=100), split bf16 output -----------
#define SAS 136
__global__ void __launch_bounds__(256, 2) conv1_k(
    const float* __restrict__ in, const float* __restrict__ wT,
    const float* __restrict__ bias)
{
    constexpr int CIN = 100, COUT = 256;
    __shared__ __align__(16) float As[2][16][SAS];
    __shared__ __align__(16) float Bs[2][16][SAS];
    constexpr int NC = 7;
    constexpr int NS = 21;
    const int tid = threadIdx.x;
    const int tx = tid & 15, ty = tid >> 4;
    const int r0 = blockIdx.x * 128;
    const int n0 = blockIdx.y * 128;

    const int sm  = tid >> 1;
    const int skq = tid & 1;
    const int aRow = r0 + sm;
    const int tt = aRow & (TT - 1);
    const int bk  = tid >> 4;
    const int bn4 = (tid & 15) * 4;

    unsigned long long acc2[8][4];
#pragma unroll
    for (int i = 0; i < 8; ++i)
#pragma unroll
        for (int j = 0; j < 4; ++j) acc2[i][j] = 0ull;

    float4 av0, av1, bv0, bv1;

    auto LOAD = [&](int s) {
        const int tap = s / NC;
        const int ccc = (s - tap * NC) * 16;
        const int ci = ccc + 8 * skq;
        const int st = tt + tap - 1;
        const bool rv = (st >= 0 && st < TT);
        const float* ap = in + (size_t)(aRow + tap - 1) * CIN + ci;
        if (ccc + 16 <= CIN) {
            if (rv) {
                av0 = *(const float4*)(ap);
                av1 = *(const float4*)(ap + 4);
            } else {
                av0 = make_float4(0.f, 0.f, 0.f, 0.f);
                av1 = av0;
            }
        } else {
            float t0[8];
#pragma unroll
            for (int q = 0; q < 8; ++q)
                t0[q] = (rv && ci + q < CIN) ? ap[q] : 0.0f;
            av0 = make_float4(t0[0], t0[1], t0[2], t0[3]);
            av1 = make_float4(t0[4], t0[5], t0[6], t0[7]);
        }
        const float* bp = wT + (size_t)(tap * 112 + ccc + bk) * COUT + n0;
        bv0 = *(const float4*)(bp + bn4);
        bv1 = *(const float4*)(bp + 64 + bn4);
    };
    auto STORE = [&](int p) {
        As[p][8 * skq + 0][sm] = av0.x;
        As[p][8 * skq + 1][sm] = av0.y;
        As[p][8 * skq + 2][sm] = av0.z;
        As[p][8 * skq + 3][sm] = av0.w;
        As[p][8 * skq + 4][sm] = av1.x;
        As[p][8 * skq + 5][sm] = av1.y;
        As[p][8 * skq + 6][sm] = av1.z;
        As[p][8 * skq + 7][sm] = av1.w;
        *(float4*)&Bs[p][bk][bn4]      = bv0;
        *(float4*)&Bs[p][bk][64 + bn4] = bv1;
    };

    LOAD(0); STORE(0);
    LOAD(1);
    __syncthreads();

    for (int s = 0; s < NS; ++s) {
        const int p = s & 1;
        if (s + 1 < NS) STORE(p ^ 1);
        if (s + 2 < NS) LOAD(s + 2);
#pragma unroll
        for (int kk = 0; kk < 16; ++kk) {
            float4 aL = *(const float4*)&As[p][kk][ty * 4];
            float4 aH = *(const float4*)&As[p][kk][64 + ty * 4];
            float4 bL = *(const float4*)&Bs[p][kk][tx * 4];
            float4 bH = *(const float4*)&Bs[p][kk][64 + tx * 4];
            unsigned long long b2[4], a2;
            pack2(b2[0], bL.x, bL.y);
            pack2(b2[1], bL.z, bL.w);
            pack2(b2[2], bH.x, bH.y);
            pack2(b2[3], bH.z, bH.w);
            float arr[8] = {aL.x, aL.y, aL.z, aL.w, aH.x, aH.y, aH.z, aH.w};
#pragma unroll
            for (int i = 0; i < 8; ++i) {
                splat2(a2, arr[i]);
#pragma unroll
                for (int j = 0; j < 4; ++j) ffma2(acc2[i][j], a2, b2[j]);
            }
        }
        __syncthreads();
    }

    float bl[8];
#pragma unroll
    for (int c = 0; c < 4; ++c) {
        bl[c]     = bias[n0 + tx * 4 + c];
        bl[4 + c] = bias[n0 + 64 + tx * 4 + c];
    }
#pragma unroll
    for (int i = 0; i < 8; ++i) {
        int m = (i < 4) ? (ty * 4 + i) : (64 + ty * 4 + (i - 4));
        int r = r0 + m;
        float v[8];
        unpack2(v[0], v[1], acc2[i][0]);
        unpack2(v[2], v[3], acc2[i][1]);
        unpack2(v[4], v[5], acc2[i][2]);
        unpack2(v[6], v[7], acc2[i][3]);
#pragma unroll
        for (int hf = 0; hf < 2; ++hf) {
            int cobase = n0 + 64 * hf + tx * 4;
#pragma unroll
            for (int q = 0; q < 2; ++q) {
                float g0 = gelu_exact(v[4 * hf + 2 * q + 0] + bl[4 * hf + 2 * q + 0]);
                float g1 = gelu_exact(v[4 * hf + 2 * q + 1] + bl[4 * hf + 2 * q + 1]);
                __nv_bfloat16 h0, l0, h1, l1;
                bsplit(g0, h0, l0);
                bsplit(g1, h1, l1);
                size_t off = (size_t)r * COUT + cobase + 2 * q;
                *(__nv_bfloat162*)&g_h1h[off] = __halves2bfloat162(h0, h1);
                *(__nv_bfloat162*)&g_h1l[off] = __halves2bfloat162(l0, l1);
            }
        }
    }
}

// ---------------- conv_mma2: presplit bf16 mma conv ------------------------
// MODE 0: split z out + rn2 atomics (conv2). MODE 1: fused MSE (dec2).
template<int CIN, int COUT, int NBPAD, int MODE>
__global__ void __launch_bounds__(256, 2) conv_mma2(
    const __nv_bfloat16* __restrict__ Ah, const __nv_bfloat16* __restrict__ Al,
    const __nv_bfloat16* __restrict__ Bh, const __nv_bfloat16* __restrict__ Bl,
    const float* __restrict__ bias, const float* __restrict__ xref)
{
    __shared__ __align__(16) __nv_bfloat16 sAh[2][128][24];
    __shared__ __align__(16) __nv_bfloat16 sAl[2][128][24];
    __shared__ __align__(16) __nv_bfloat16 sBh[2][64][24];
    __shared__ __align__(16) __nv_bfloat16 sBl[2][64][24];
    constexpr int NC = CIN / 16;
    constexpr int NS = 3 * NC;

    const int tid = threadIdx.x;
    const int w = tid >> 5, l = tid & 31;
    const int r0 = blockIdx.x * 128;
    const int n0 = blockIdx.y * 64;

    const int arow = tid >> 1;
    const int adh  = (tid & 1) * 8;
    const int aRow = r0 + arow;
    const int tt = aRow & (TT - 1);
    const int brow = tid >> 2;
    const int bdq  = (tid & 3) * 4;

    float acc[8][4];
#pragma unroll
    for (int j = 0; j < 8; ++j)
#pragma unroll
        for (int c = 0; c < 4; ++c) acc[j][c] = 0.0f;

    uint4 avh, avl;
    uint2 bvh, bvl;
    auto LDG = [&](int s) {
        const int tap = s / NC;
        const int ccc = (s - tap * NC) * 16;
        const int st = tt + tap - 1;
        if (st >= 0 && st < TT) {
            size_t aoff = (size_t)(aRow + tap - 1) * CIN + ccc + adh;
            avh = *(const uint4*)(Ah + aoff);
            avl = *(const uint4*)(Al + aoff);
        } else {
            avh = make_uint4(0u, 0u, 0u, 0u);
            avl = avh;
        }
        size_t boff = (size_t)(tap * NBPAD + n0 + brow) * CIN + ccc + bdq;
        bvh = *(const uint2*)(Bh + boff);
        bvl = *(const uint2*)(Bl + boff);
    };
    auto STS = [&](int p) {
        *(uint4*)&sAh[p][arow][adh] = avh;
        *(uint4*)&sAl[p][arow][adh] = avl;
        *(uint2*)&sBh[p][brow][bdq] = bvh;
        *(uint2*)&sBl[p][brow][bdq] = bvl;
    };

    const int arl = l & 15, ach = (l >> 4) * 8;
    const int bg = l >> 3;
    const int bn = ((bg >= 2) ? 8 : 0) + (l & 7);
    const int bkoff = (bg & 1) * 8;

    LDG(0); STS(0);
    __syncthreads();

    for (int s = 0; s < NS; ++s) {
        const int p = s & 1;
        if (s + 1 < NS) LDG(s + 1);

        uint32_t ah[4], al[4];
        LDSM_X4(ah[0], ah[1], ah[2], ah[3], smem_u32(&sAh[p][w * 16 + arl][ach]));
        LDSM_X4(al[0], al[1], al[2], al[3], smem_u32(&sAl[p][w * 16 + arl][ach]));
        uint32_t bh[4][4], blr[4][4];
#pragma unroll
        for (int nb = 0; nb < 4; ++nb) {
            LDSM_X4(bh[nb][0], bh[nb][1], bh[nb][2], bh[nb][3],
                    smem_u32(&sBh[p][nb * 16 + bn][bkoff]));
            LDSM_X4(blr[nb][0], blr[nb][1], blr[nb][2], blr[nb][3],
                    smem_u32(&sBl[p][nb * 16 + bn][bkoff]));
        }
#pragma unroll
        for (int nb = 0; nb < 4; ++nb) {
#pragma unroll
            for (int h = 0; h < 2; ++h) {
                const int j = nb * 2 + h;
                MMA_BF16(acc[j], ah, bh[nb][2 * h], bh[nb][2 * h + 1]);
                MMA_BF16(acc[j], ah, blr[nb][2 * h], blr[nb][2 * h + 1]);
                MMA_BF16(acc[j], al, bh[nb][2 * h], bh[nb][2 * h + 1]);
            }
        }
        if (s + 1 < NS) STS(p ^ 1);
        __syncthreads();
    }

    const int row0 = r0 + w * 16 + (l >> 2);
    const int col0 = n0 + 2 * (l & 3);
    if (MODE == 0) {
        float rn0 = 0.0f, rn1 = 0.0f;
#pragma unroll
        for (int j = 0; j < 8; ++j) {
            int c0 = col0 + j * 8;
            float b0 = bias[c0], b1 = bias[c0 + 1];
            float g00 = gelu_exact(acc[j][0] + b0);
            float g01 = gelu_exact(acc[j][1] + b1);
            float g10 = gelu_exact(acc[j][2] + b0);
            float g11 = gelu_exact(acc[j][3] + b1);
            rn0 += g00 * g00 + g01 * g01;
            rn1 += g10 * g10 + g11 * g11;
            __nv_bfloat16 h0, l0, h1, l1;
            bsplit(g00, h0, l0); bsplit(g01, h1, l1);
            *(__nv_bfloat162*)&g_zh[(size_t)row0 * COUT + c0] = __halves2bfloat162(h0, h1);
            *(__nv_bfloat162*)&g_zl[(size_t)row0 * COUT + c0] = __halves2bfloat162(l0, l1);
            bsplit(g10, h0, l0); bsplit(g11, h1, l1);
            *(__nv_bfloat162*)&g_zh[(size_t)(row0 + 8) * COUT + c0] = __halves2bfloat162(h0, h1);
            *(__nv_bfloat162*)&g_zl[(size_t)(row0 + 8) * COUT + c0] = __halves2bfloat162(l0, l1);
        }
        atomicAdd(&g_rn2[row0], rn0);
        atomicAdd(&g_rn2[row0 + 8], rn1);
    } else {
        float local = 0.0f;
#pragma unroll
        for (int j = 0; j < 8; ++j) {
            int c0 = col0 + j * 8;
            float b0 = (c0 < COUT) ? bias[c0] : 0.f;
            float b1 = (c0 + 1 < COUT) ? bias[c0 + 1] : 0.f;
            float g00 = gelu_exact(acc[j][0] + b0);
            float g01 = gelu_exact(acc[j][1] + b1);
            float g10 = gelu_exact(acc[j][2] + b0);
            float g11 = gelu_exact(acc[j][3] + b1);
            if (c0 < COUT) {
                float d0 = xref[(size_t)row0 * COUT + c0] - g00;
                float d1 = xref[(size_t)(row0 + 8) * COUT + c0] - g10;
                local += d0 * d0 + d1 * d1;
            }
            if (c0 + 1 < COUT) {
                float d0 = xref[(size_t)row0 * COUT + c0 + 1] - g01;
                float d1 = xref[(size_t)(row0 + 8) * COUT + c0 + 1] - g11;
                local += d0 * d0 + d1 * d1;
            }
        }
        __shared__ float red[256];
        red[tid] = local;
        __syncthreads();
        for (int ss = 128; ss > 0; ss >>= 1) {
            if (tid < ss) red[tid] += red[tid + ss];
            __syncthreads();
        }
        if (tid == 0) atomicAdd(&g_acc[1], red[0]);
    }
}

// ---------------- vq_gemm: presplit bf16 mma, dist store -------------------
__global__ void __launch_bounds__(256, 2) vq_gemm_mma() {
    __shared__ __align__(16) __nv_bfloat16 sAh[2][128][24];
    __shared__ __align__(16) __nv_bfloat16 sAl[2][128][24];
    __shared__ __align__(16) __nv_bfloat16 sBh[2][64][24];
    __shared__ __align__(16) __nv_bfloat16 sBl[2][64][24];

    const int tid = threadIdx.x;
    const int w = tid >> 5, l = tid & 31;
    const int r0 = blockIdx.x * 128;
    const int k0 = blockIdx.y * 64;

    const int arow = tid >> 1;
    const int adh  = (tid & 1) * 8;
    const size_t abase = (size_t)(r0 + arow) * DD + adh;
    const int brow = tid >> 2;
    const int bdq  = (tid & 3) * 4;
    const size_t bbase = (size_t)(k0 + brow) * DD + bdq;

    float acc[8][4];
#pragma unroll
    for (int j = 0; j < 8; ++j)
#pragma unroll
        for (int c = 0; c < 4; ++c) acc[j][c] = 0.0f;

    uint4 avh, avl;
    uint2 bvh, bvl;
    auto LDG = [&](int ks) {
        avh = *(const uint4*)(g_zh + abase + ks * 16);
        avl = *(const uint4*)(g_zl + abase + ks * 16);
        bvh = *(const uint2*)(g_cbh + bbase + ks * 16);
        bvl = *(const uint2*)(g_cbl + bbase + ks * 16);
    };
    auto STS = [&](int p) {
        *(uint4*)&sAh[p][arow][adh] = avh;
        *(uint4*)&sAl[p][arow][adh] = avl;
        *(uint2*)&sBh[p][brow][bdq] = bvh;
        *(uint2*)&sBl[p][brow][bdq] = bvl;
    };

    const int arl = l & 15, ach = (l >> 4) * 8;
    const int bg = l >> 3;
    const int bn = ((bg >= 2) ? 8 : 0) + (l & 7);
    const int bkoff = (bg & 1) * 8;

    LDG(0); STS(0);
    __syncthreads();

    for (int ks = 0; ks < 32; ++ks) {
        const int p = ks & 1;
        if (ks + 1 < 32) LDG(ks + 1);

        uint32_t ah[4], al[4];
        LDSM_X4(ah[0], ah[1], ah[2], ah[3], smem_u32(&sAh[p][w * 16 + arl][ach]));
        LDSM_X4(al[0], al[1], al[2], al[3], smem_u32(&sAl[p][w * 16 + arl][ach]));
        uint32_t bh[4][4], blr[4][4];
#pragma unroll
        for (int nb = 0; nb < 4; ++nb) {
            LDSM_X4(bh[nb][0], bh[nb][1], bh[nb][2], bh[nb][3],
                    smem_u32(&sBh[p][nb * 16 + bn][bkoff]));
            LDSM_X4(blr[nb][0], blr[nb][1], blr[nb][2], blr[nb][3],
                    smem_u32(&sBl[p][nb * 16 + bn][bkoff]));
        }
#pragma unroll
        for (int nb = 0; nb < 4; ++nb) {
#pragma unroll
            for (int h = 0; h < 2; ++h) {
                const int j = nb * 2 + h;
                MMA_BF16(acc[j], ah, bh[nb][2 * h], bh[nb][2 * h + 1]);
                MMA_BF16(acc[j], ah, blr[nb][2 * h], blr[nb][2 * h + 1]);
                MMA_BF16(acc[j], al, bh[nb][2 * h], bh[nb][2 * h + 1]);
            }
        }
        if (ks + 1 < 32) STS(p ^ 1);
        __syncthreads();
    }

    const int row0 = r0 + w * 16 + (l >> 2);
    const int col0 = k0 + 2 * (l & 3);
#pragma unroll
    for (int j = 0; j < 8; ++j) {
        *(float2*)&g_dist[(size_t)row0 * KK + col0 + j * 8] =
            make_float2(acc[j][0], acc[j][1]);
        *(float2*)&g_dist[(size_t)(row0 + 8) * KK + col0 + j * 8] =
            make_float2(acc[j][2], acc[j][3]);
    }
}

// ---------------- shared pipelined-GEMM body (generalized B) --------------
#define GEMM_BODY(AROW_EXPR, BBASE, BSTRIDE)                                   \
    const int sm  = tid >> 1;                                                  \
    const int skq = tid & 1;                                                   \
    const int arow = (AROW_EXPR);                                              \
    const float* aptr = Abase + (size_t)arow * DD + 8 * skq;                   \
    const int bk  = tid >> 4;                                                  \
    const int bn4 = (tid & 15) * 4;                                            \
    const float* bbase = (BBASE) + (size_t)bk * (BSTRIDE) + k0;                \
    unsigned long long acc2[8][4];                                             \
    _Pragma("unroll")                                                          \
    for (int i = 0; i < 8; ++i)                                                \
        _Pragma("unroll")                                                      \
        for (int j = 0; j < 4; ++j) acc2[i][j] = 0ull;                         \
    float4 av0, av1, bv0, bv1;                                                 \
    auto LOAD = [&](int cc) {                                                  \
        av0 = *(const float4*)(aptr + cc);                                     \
        av1 = *(const float4*)(aptr + cc + 4);                                 \
        const float* bp = bbase + (size_t)cc * (BSTRIDE);                      \
        bv0 = *(const float4*)(bp + bn4);                                      \
        bv1 = *(const float4*)(bp + 64 + bn4);                                 \
    };                                                                         \
    auto STORE = [&](int p) {                                                  \
        As[p][8 * skq + 0][sm] = av0.x;                                        \
        As[p][8 * skq + 1][sm] = av0.y;                                        \
        As[p][8 * skq + 2][sm] = av0.z;                                        \
        As[p][8 * skq + 3][sm] = av0.w;                                        \
        As[p][8 * skq + 4][sm] = av1.x;                                        \
        As[p][8 * skq + 5][sm] = av1.y;                                        \
        As[p][8 * skq + 6][sm] = av1.z;                                        \
        As[p][8 * skq + 7][sm] = av1.w;                                        \
        *(float4*)&Bs[p][bk][bn4]      = bv0;                                  \
        *(float4*)&Bs[p][bk][64 + bn4] = bv1;                                  \
    };                                                                         \
    LOAD(0); STORE(0);                                                         \
    LOAD(16);                                                                  \
    __syncthreads();                                                           \
    for (int ch = 0; ch < 32; ++ch) {                                          \
        const int p = ch & 1;                                                  \
        if (ch + 1 < 32) STORE(p ^ 1);                                         \
        if (ch + 2 < 32) LOAD((ch + 2) * 16);                                  \
        _Pragma("unroll")                                                      \
        for (int kk = 0; kk < 16; ++kk) {                                      \
            float4 aL = *(const float4*)&As[p][kk][ty * 4];                    \
            float4 aH = *(const float4*)&As[p][kk][64 + ty * 4];               \
            float4 bL = *(const float4*)&Bs[p][kk][tx * 4];                    \
            float4 bH = *(const float4*)&Bs[p][kk][64 + tx * 4];               \
            unsigned long long b2[4], a2;                                      \
            pack2(b2[0], bL.x, bL.y);                                          \
            pack2(b2[1], bL.z, bL.w);                                          \
            pack2(b2[2], bH.x, bH.y);                                          \
            pack2(b2[3], bH.z, bH.w);                                          \
            float arr[8] = {aL.x, aL.y, aL.z, aL.w, aH.x, aH.y, aH.z, aH.w};   \
            _Pragma("unroll")                                                  \
            for (int i = 0; i < 8; ++i) {                                      \
                splat2(a2, arr[i]);                                            \
                _Pragma("unroll")                                              \
                for (int j = 0; j < 4; ++j) ffma2(acc2[i][j], a2, b2[j]);      \
            }                                                                  \
        }                                                                      \
        __syncthreads();                                                       \
    }

// ---------------- Gram GEMM: G = cb · cbT + csq = diag(G) ------------------
__global__ void __launch_bounds__(256, 2) gram_gemm(const float* __restrict__ cb) {
    __shared__ __align__(16) float As[2][16][SAS];
    __shared__ __align__(16) float Bs[2][16][SAS];
    const int tid = threadIdx.x;
    const int tx = tid & 15, ty = tid >> 4;
    const int r0 = blockIdx.x * 128;
    const int k0 = blockIdx.y * 128;
    const float* Abase = cb;
    GEMM_BODY(r0 + (tid >> 1), g_cbT, KK)

#pragma unroll
    for (int i = 0; i < 8; ++i) {
        int m = (i < 4) ? (ty * 4 + i) : (64 + ty * 4 + (i - 4));
        int row = r0 + m;
        float d0, d1, d2, d3;
        unpack2(d0, d1, acc2[i][0]);
        unpack2(d2, d3, acc2[i][1]);
        *(float4*)&g_G[(size_t)row * KK + k0 + tx * 4] = make_float4(d0, d1, d2, d3);
        if (r0 == k0) {
            int c0 = k0 + tx * 4;
            if (row >= c0 && row < c0 + 4) {
                float dd[4] = {d0, d1, d2, d3};
                g_csq[row] = dd[row - c0];
            }
        }
        unpack2(d0, d1, acc2[i][2]);
        unpack2(d2, d3, acc2[i][3]);
        *(float4*)&g_G[(size_t)row * KK + k0 + 64 + tx * 4] = make_float4(d0, d1, d2, d3);
        if (r0 == k0) {
            int c1 = k0 + 64 + tx * 4;
            if (row >= c1 && row < c1 + 4) {
                float dd[4] = {d0, d1, d2, d3};
                g_csq[row] = dd[row - c1];
            }
        }
    }
}

// ---------------- U GEMM: U[tap] = cb · W1_tap^T  (grid 8 x 2 x 3) ---------
__global__ void __launch_bounds__(256, 2) u_gemm(const float* __restrict__ cb) {
    __shared__ __align__(16) float As[2][16][SAS];
    __shared__ __align__(16) float Bs[2][16][SAS];
    const int tid = threadIdx.x;
    const int tx = tid & 15, ty = tid >> 4;
    const int r0 = blockIdx.x * 128;
    const int k0 = blockIdx.y * 128;
    const int tap = blockIdx.z;
    const float* Abase = cb;
    const float* wt3 = g_wT + WT_O3 + (size_t)tap * 512 * 256;
    GEMM_BODY(r0 + (tid >> 1), wt3, 256)

#pragma unroll
    for (int i = 0; i < 8; ++i) {
        int m = (i < 4) ? (ty * 4 + i) : (64 + ty * 4 + (i - 4));
        int row = r0 + m;
        float* urow = &g_U[((size_t)tap * KK + row) * 256 + k0];
        float d0, d1, d2, d3;
        unpack2(d0, d1, acc2[i][0]);
        unpack2(d2, d3, acc2[i][1]);
        *(float4*)(urow + tx * 4) = make_float4(d0, d1, d2, d3);
        unpack2(d0, d1, acc2[i][2]);
        unpack2(d2, d3, acc2[i][3]);
        *(float4*)(urow + 64 + tx * 4) = make_float4(d0, d1, d2, d3);
    }
}

// ---------------- init_small ----------------
__global__ void init_small() {
    int tid = threadIdx.x;  // 32
    if (tid < 8) {
        unsigned a, b;
        tf2x32(0u, 42u, 0u, (unsigned)tid, a, b);
        g_fk[2 * tid] = a;
        g_fk[2 * tid + 1] = b;
    }
    if (tid < 2) g_acc[tid] = 0.0f;
    if (tid == 0) {
        float ghi = gumbel_from_bits(0xFFFFFFFFu);
        float glo = gumbel_from_bits(0u);
        g_window = (ghi - glo) + 0.5f;
    }
}

// ---------------- pick: all 8 VQ stages per row -> g_sel -------------------
__global__ void __launch_bounds__(256) vq_pick() {
    const int bt = blockIdx.x;
    const int tid = threadIdx.x;
    __shared__ unsigned sMaxU;
    __shared__ unsigned long long sBest;
    __shared__ float sDotSel;
    __shared__ int sSel[8];

    if (tid == 0) { sMaxU = 0u; sBest = 0ull; }

    float d[4], cs[4], s[4];
    const float* drow = &g_dist[(size_t)bt * KK];
#pragma unroll
    for (int j = 0; j < 4; ++j) {
        d[j] = drow[tid + 256 * j];
        cs[j] = g_csq[tid + 256 * j];
        s[j] = fmaf(20.0f, d[j], -10.0f * cs[j]);
    }
    const float win = g_window;
    const unsigned btL = (bt < 8192) ? (unsigned)bt : (unsigned)(bt - 8192);
    const bool hi = (bt >= 8192);
    float rn2 = (tid == 0) ? g_rn2[bt] : 0.0f;
    float commit = 0.0f;
    __syncthreads();

    for (int i = 0; i < 8; ++i) {
        float lm = fmaxf(fmaxf(s[0], s[1]), fmaxf(s[2], s[3]));
#pragma unroll
        for (int off = 16; off > 0; off >>= 1)
            lm = fmaxf(lm, __shfl_xor_sync(0xffffffffu, lm, off));
        if ((tid & 31) == 0) atomicMax(&sMaxU, fmap(lm));
        __syncthreads();
        const float tau = unfmap(sMaxU) - win;

        const unsigned fk0 = g_fk[2 * i], fk1 = g_fk[2 * i + 1];
#pragma unroll
        for (int j = 0; j < 4; ++j) {
            if (s[j] >= tau) {
                unsigned k = (unsigned)(tid + 256 * j);
                unsigned n = btL * 1024u + k;
                unsigned b0, b1;
                tf2x32(fk0, fk1, n, n + HALF_N, b0, b1);
                float g = gumbel_from_bits(hi ? b1 : b0);
                float sc = s[j] + g;
                unsigned long long cand =
                    ((unsigned long long)fmap(sc) << 32) | (unsigned long long)(~k);
                atomicMax(&sBest, cand);
            }
        }
        __syncthreads();
        const unsigned sel = ~(unsigned)(sBest & 0xffffffffull);
        if (tid == (int)(sel & 255u)) sDotSel = d[sel >> 8];
        __syncthreads();
        if (tid == 0) {
            float rn2n = rn2 - 2.0f * sDotSel + g_csq[sel];
            commit += rn2n;
            rn2 = rn2n;
            sSel[i] = (int)sel;
            sMaxU = 0u;
            sBest = 0ull;
        }
        if (i < 7) {
            const float* grow = &g_G[(size_t)sel * KK];
#pragma unroll
            for (int j = 0; j < 4; ++j) {
                d[j] -= grow[tid + 256 * j];
                s[j] = fmaf(20.0f, d[j], -10.0f * cs[j]);
            }
        }
        __syncthreads();
    }

    if (tid < 8) g_sel[bt * 8 + tid] = sSel[tid];
    if (tid == 0) atomicAdd(&g_acc[0], commit);
}

// ---------------- dec1 gather: h1 = gelu(bias + sum U rows), split out -----
__global__ void __launch_bounds__(256) dec1_gather(const float* __restrict__ bias) {
    const int bt = blockIdx.x;
    const int c = threadIdx.x;
    __shared__ int sIdx[24];

    if (c < 24) {
        int tap = c >> 3, i = c & 7;
        int t = bt & (TT - 1);
        int st = t + tap - 1;
        int idx = -1;
        if (st >= 0 && st < TT)
            idx = tap * KK + g_sel[(bt + tap - 1) * 8 + i];
        sIdx[c] = idx;
    }
    __syncthreads();

    float acc = bias[c];
#pragma unroll
    for (int j = 0; j < 24; ++j) {
        int idx = sIdx[j];
        if (idx >= 0) acc += g_U[(size_t)idx * 256 + c];
    }
    float g = gelu_exact(acc);
    __nv_bfloat16 h, l;
    bsplit(g, h, l);
    g_h1h[(size_t)bt * 256 + c] = h;
    g_h1l[(size_t)bt * 256 + c] = l;
}

__global__ void finalize_k(float* __restrict__ out) {
    out[0] = g_acc[1] * (1.0f / 1638400.0f)
           + g_acc[0] * (1.0f / 67108864.0f);
}

// ---------------- streams/events (created once, pre-baseline) --------------
struct SideStream {
    cudaStream_t s;
    cudaEvent_t fork, wtev, join1, join2;
    SideStream() {
        cudaStreamCreateWithFlags(&s, cudaStreamNonBlocking);
        cudaEventCreateWithFlags(&fork, cudaEventDisableTiming);
        cudaEventCreateWithFlags(&wtev, cudaEventDisableTiming);
        cudaEventCreateWithFlags(&join1, cudaEventDisableTiming);
        cudaEventCreateWithFlags(&join2, cudaEventDisableTiming);
    }
};
static SideStream g_ss;

// ---------------- host launcher (graph-capturable, alloc-free) -------------
extern "C" void kernel_launch(void* const* d_in, const int* in_sizes, int n_in,
                              void* d_out, int out_size) {
    const float* x   = (const float*)d_in[0];
    const float* ew1 = (const float*)d_in[1];
    const float* eb1 = (const float*)d_in[2];
    const float* ew2 = (const float*)d_in[3];
    const float* eb2 = (const float*)d_in[4];
    const float* cb  = (const float*)d_in[5];
    const float* dw1 = (const float*)d_in[6];
    const float* db1 = (const float*)d_in[7];
    const float* dw2 = (const float*)d_in[8];
    const float* db2 = (const float*)d_in[9];
    float* out = (float*)d_out;

    float* wT;
    __nv_bfloat16 *h1h, *h1l, *wtth, *wttl, *cbh, *cbl;
    cudaGetSymbolAddress((void**)&wT,   g_wT);
    cudaGetSymbolAddress((void**)&h1h,  g_h1h);
    cudaGetSymbolAddress((void**)&h1l,  g_h1l);
    cudaGetSymbolAddress((void**)&wtth, g_wtth);
    cudaGetSymbolAddress((void**)&wttl, g_wttl);
    cudaGetSymbolAddress((void**)&cbh,  g_cbh);
    cudaGetSymbolAddress((void**)&cbl,  g_cbl);

    // fork side branch: cbT -> Gram(+csq) -> cb split -> init_small
    cudaEventRecord(g_ss.fork, 0);
    cudaStreamWaitEvent(g_ss.s, g_ss.fork, 0);
    transpose_cb<<<dim3(KK / 32, DD / 32), dim3(32, 8), 0, g_ss.s>>>(cb);
    gram_gemm<<<dim3(8, 8), 256, 0, g_ss.s>>>(cb);
    cb_split<<<KK * DD / 256, 256, 0, g_ss.s>>>(cb);
    init_small<<<1, 32, 0, g_ss.s>>>();
    cudaEventRecord(g_ss.join1, g_ss.s);

    // main branch: weights (both layouts) + rn2 zero -> encoder
    transpose_w_all<<<(WT_END + WTT_END + 255) / 256, 256>>>(ew1, ew2, dw1, dw2);
    cudaEventRecord(g_ss.wtev, 0);

    // side: U = cb · dec_w1^T per tap (needs wT3) — overlaps encoder convs
    cudaStreamWaitEvent(g_ss.s, g_ss.wtev, 0);
    u_gemm<<<dim3(8, 2, 3), 256, 0, g_ss.s>>>(cb);
    cudaEventRecord(g_ss.join2, g_ss.s);

    conv1_k<<<dim3(128, 2), 256>>>(x, wT + WT_O1, eb1);
    conv_mma2<256, 512, 512, 0><<<dim3(128, 8), 256>>>(
        h1h, h1l, wtth + WTT_O2, wttl + WTT_O2, eb2, nullptr);

    // join: vq needs cbT / G / csq / cb-split / fk / window
    cudaStreamWaitEvent(0, g_ss.join1, 0);
    vq_gemm_mma<<<dim3(128, 16), 256>>>();
    vq_pick<<<BT, 256>>>();

    // decoder: gathered dec1 (needs U), then dec2 mma conv with fused MSE
    cudaStreamWaitEvent(0, g_ss.join2, 0);
    dec1_gather<<<BT, 256>>>(db1);
    conv_mma2<256, 100, 128, 1><<<dim3(128, 2), 256>>>(
        h1h, h1l, wtth + WTT_O4, wttl + WTT_O4, db2, x);

    finalize_k<<<1, 1>>>(out);
}

// round 16
// speedup vs baseline: 1.1822x; 1.1822x over previous
#include <cuda_runtime.h>
#include <cuda_bf16.h>
#include <cstdint>

#define TT 2048
#define BT 16384
#define DD 512
#define KK 1024
#define HALF_N 8388608u   // BT*KK/2

// ---------------- scratch (static device allocations only) ----------------
__device__ float g_h1[BT * 256];
__device__ float g_res[BT * DD];          // encoder output z
__device__ float g_cbT[DD * KK];          // codebook transposed [d][k]
__device__ float g_dist[BT * KK];         // dot products <z, c_k>  (64MB)
__device__ float g_G[KK * KK];            // Gram matrix cb·cbT     (4MB)
__device__ float g_csq[KK];               // = diag(G)
__device__ float g_wT[1048576];           // [tap][ci][co] fp32 weights (4MB)
__device__ float g_wTT[491520];           // [tap][co][ci] for mma convs (2MB)
__device__ float g_U[3 * KK * 256];       // U[tap][k][co] = cb·W1_tap^T (3MB)
__device__ int   g_sel[BT * 8];
__device__ unsigned g_fk[16];
__device__ float g_window;
__device__ float g_acc[2];   // [0]=commit sum, [1]=mse sum

#define WT_O1 0
#define WT_O2 86016
#define WT_O3 479232
#define WT_O4 872448
#define WT_END 970752
#define WTT_O2 0
#define WTT_O4 393216
#define WTT_END 491520

// ---------------- packed f32x2 helpers ----------------
__device__ __forceinline__ void splat2(unsigned long long& d, float a) {
    asm("mov.b64 %0, {%1, %1};" : "=l"(d) : "f"(a));
}
__device__ __forceinline__ void pack2(unsigned long long& d, float a, float b) {
    asm("mov.b64 %0, {%1, %2};" : "=l"(d) : "f"(a), "f"(b));
}
__device__ __forceinline__ void unpack2(float& a, float& b, unsigned long long d) {
    asm("mov.b64 {%0, %1}, %2;" : "=f"(a), "=f"(b) : "l"(d));
}
__device__ __forceinline__ void ffma2(unsigned long long& acc,
                                      unsigned long long a, unsigned long long b) {
    asm("fma.rn.f32x2 %0, %1, %2, %0;" : "+l"(acc) : "l"(a), "l"(b));
}

// ---------------- mma.sync / ldmatrix helpers ----------------
__device__ __forceinline__ uint32_t smem_u32(const void* p) {
    uint32_t a;
    asm("{ .reg .u64 t; cvta.to.shared.u64 t, %1; cvt.u32.u64 %0, t; }"
        : "=r"(a) : "l"(p));
    return a;
}
#define LDSM_X4(r0, r1, r2, r3, addr) \
    asm volatile("ldmatrix.sync.aligned.m8n8.x4.shared.b16 {%0,%1,%2,%3}, [%4];" \
        : "=r"(r0), "=r"(r1), "=r"(r2), "=r"(r3) : "r"(addr))
#define MMA_BF16(d, a, b0, b1) \
    asm volatile("mma.sync.aligned.m16n8k16.row.col.f32.bf16.bf16.f32 " \
        "{%0,%1,%2,%3}, {%4,%5,%6,%7}, {%8,%9}, {%0,%1,%2,%3};" \
        : "+f"((d)[0]), "+f"((d)[1]), "+f"((d)[2]), "+f"((d)[3]) \
        : "r"((a)[0]), "r"((a)[1]), "r"((a)[2]), "r"((a)[3]), "r"(b0), "r"(b1))

// ---------------- JAX threefry2x32 (exact) ----------------
__host__ __device__ inline void tf2x32(unsigned k0, unsigned k1,
                                       unsigned x0, unsigned x1,
                                       unsigned& o0, unsigned& o1) {
    unsigned ks2 = k0 ^ k1 ^ 0x1BD11BDAu;
    x0 += k0; x1 += k1;
#define TF_RND(r) { x0 += x1; x1 = (x1 << (r)) | (x1 >> (32 - (r))); x1 ^= x0; }
    TF_RND(13) TF_RND(15) TF_RND(26) TF_RND(6)
    x0 += k1;  x1 += ks2 + 1u;
    TF_RND(17) TF_RND(29) TF_RND(16) TF_RND(24)
    x0 += ks2; x1 += k0 + 2u;
    TF_RND(13) TF_RND(15) TF_RND(26) TF_RND(6)
    x0 += k0;  x1 += k1 + 3u;
    TF_RND(17) TF_RND(29) TF_RND(16) TF_RND(24)
    x0 += k1;  x1 += ks2 + 4u;
    TF_RND(13) TF_RND(15) TF_RND(26) TF_RND(6)
    x0 += ks2; x1 += k0 + 5u;
#undef TF_RND
    o0 = x0; o1 = x1;
}

__device__ inline float gumbel_from_bits(unsigned bits) {
    float f = __uint_as_float((bits >> 9) | 0x3f800000u) - 1.0f;
    float u = (f == 0.0f) ? 1.17549435e-38f : f;
    return -__logf(-__logf(u));
}

__device__ inline unsigned fmap(float f) {
    unsigned u = __float_as_uint(f);
    return (u & 0x80000000u) ? ~u : (u | 0x80000000u);
}
__device__ inline float unfmap(unsigned u) {
    unsigned v = (u & 0x80000000u) ? (u ^ 0x80000000u) : ~u;
    return __uint_as_float(v);
}

__device__ inline float gelu_exact(float v) {
    return 0.5f * v * (1.0f + erff(v * 0.7071067811865476f));
}

// ---------------- codebook transpose ----------------
__global__ void transpose_cb(const float* __restrict__ cb) {
    __shared__ float t[32][33];
    int k0 = blockIdx.x * 32;
    int d0 = blockIdx.y * 32;
    int tx = threadIdx.x, ty = threadIdx.y;  // 32 x 8
    for (int l = 0; l < 32; l += 8)
        t[ty + l][tx] = cb[(k0 + ty + l) * DD + d0 + tx];
    __syncthreads();
    for (int l = 0; l < 32; l += 8)
        g_cbT[(d0 + ty + l) * KK + k0 + tx] = t[tx][ty + l];
}

// ---------------- merged weight transpose (both layouts) -------------------
__device__ __forceinline__ void wt_range(int local, const float* __restrict__ w,
                                         int CIN, int COUT, int CIN16, int PAD,
                                         float* __restrict__ dst) {
    int co = local % PAD;
    int rest = local / PAD;
    int ci = rest % CIN16;
    int tap = rest / CIN16;
    float v = 0.0f;
    if (ci < CIN && co < COUT)
        v = w[((size_t)co * CIN + ci) * 3 + tap];
    dst[local] = v;
}
__device__ __forceinline__ void wtt_range(int local, const float* __restrict__ w,
                                          int CIN, int COUT, int ROWS,
                                          float* __restrict__ dst) {
    int ci = local % CIN;
    int rest = local / CIN;
    int co = rest % ROWS;
    int tap = rest / ROWS;
    float v = 0.0f;
    if (co < COUT)
        v = w[((size_t)co * CIN + ci) * 3 + tap];
    dst[local] = v;
}
__global__ void transpose_w_all(const float* __restrict__ w1, const float* __restrict__ w2,
                                const float* __restrict__ w3, const float* __restrict__ w4) {
    int idx = blockIdx.x * 256 + threadIdx.x;
    if (idx < WT_END) {
        if (idx < WT_O2)      wt_range(idx - WT_O1, w1, 100, 256, 112, 256, g_wT + WT_O1);
        else if (idx < WT_O3) wt_range(idx - WT_O2, w2, 256, 512, 256, 512, g_wT + WT_O2);
        else if (idx < WT_O4) wt_range(idx - WT_O3, w3, 512, 256, 512, 256, g_wT + WT_O3);
        else                  wt_range(idx - WT_O4, w4, 256, 100, 256, 128, g_wT + WT_O4);
    } else {
        int j = idx - WT_END;
        if (j >= WTT_END) return;
        if (j < WTT_O4) wtt_range(j - WTT_O2, w2, 256, 512, 512, g_wTT + WTT_O2);
        else            wtt_range(j - WTT_O4, w4, 256, 100, 128, g_wTT + WTT_O4);
    }
}

// ---------------- conv3f: FFMA2 conv (kept for conv1, CIN=100) -------------
#define SAS 136
template<int CIN, int COUT, int COUT_PAD, bool FUSE_MSE>
__global__ void __launch_bounds__(256, 2) conv3f(
    const float* __restrict__ in, const float* __restrict__ wT,
    const float* __restrict__ bias, float* __restrict__ out,
    const float* __restrict__ xref)
{
    __shared__ __align__(16) float As[2][16][SAS];
    __shared__ __align__(16) float Bs[2][16][SAS];
    constexpr int NC = (CIN + 15) / 16;
    constexpr int CIN16 = NC * 16;
    constexpr int NS = 3 * NC;
    const int tid = threadIdx.x;
    const int tx = tid & 15, ty = tid >> 4;
    const int r0 = blockIdx.x * 128;
    const int n0 = blockIdx.y * 128;

    const int sm  = tid >> 1;
    const int skq = tid & 1;
    const int aRow = r0 + sm;
    const int tt = aRow & (TT - 1);
    const int bk  = tid >> 4;
    const int bn4 = (tid & 15) * 4;

    unsigned long long acc2[8][4];
#pragma unroll
    for (int i = 0; i < 8; ++i)
#pragma unroll
        for (int j = 0; j < 4; ++j) acc2[i][j] = 0ull;

    float4 av0, av1, bv0, bv1;

    auto LOAD = [&](int s) {
        const int tap = s / NC;
        const int ccc = (s - tap * NC) * 16;
        const int ci = ccc + 8 * skq;
        const int st = tt + tap - 1;
        const bool rv = (st >= 0 && st < TT);
        const float* ap = in + (size_t)(aRow + tap - 1) * CIN + ci;
        if ((CIN % 16 == 0) || (ccc + 16 <= CIN)) {
            if (rv) {
                av0 = *(const float4*)(ap);
                av1 = *(const float4*)(ap + 4);
            } else {
                av0 = make_float4(0.f, 0.f, 0.f, 0.f);
                av1 = av0;
            }
        } else {
            float t0[8];
#pragma unroll
            for (int q = 0; q < 8; ++q)
                t0[q] = (rv && ci + q < CIN) ? ap[q] : 0.0f;
            av0 = make_float4(t0[0], t0[1], t0[2], t0[3]);
            av1 = make_float4(t0[4], t0[5], t0[6], t0[7]);
        }
        const float* bp = wT + (size_t)(tap * CIN16 + ccc + bk) * COUT_PAD + n0;
        bv0 = *(const float4*)(bp + bn4);
        bv1 = *(const float4*)(bp + 64 + bn4);
    };
    auto STORE = [&](int p) {
        As[p][8 * skq + 0][sm] = av0.x;
        As[p][8 * skq + 1][sm] = av0.y;
        As[p][8 * skq + 2][sm] = av0.z;
        As[p][8 * skq + 3][sm] = av0.w;
        As[p][8 * skq + 4][sm] = av1.x;
        As[p][8 * skq + 5][sm] = av1.y;
        As[p][8 * skq + 6][sm] = av1.z;
        As[p][8 * skq + 7][sm] = av1.w;
        *(float4*)&Bs[p][bk][bn4]      = bv0;
        *(float4*)&Bs[p][bk][64 + bn4] = bv1;
    };

    LOAD(0); STORE(0);
    LOAD(1);
    __syncthreads();

    for (int s = 0; s < NS; ++s) {
        const int p = s & 1;
        if (s + 1 < NS) STORE(p ^ 1);
        if (s + 2 < NS) LOAD(s + 2);
#pragma unroll
        for (int kk = 0; kk < 16; ++kk) {
            float4 aL = *(const float4*)&As[p][kk][ty * 4];
            float4 aH = *(const float4*)&As[p][kk][64 + ty * 4];
            float4 bL = *(const float4*)&Bs[p][kk][tx * 4];
            float4 bH = *(const float4*)&Bs[p][kk][64 + tx * 4];
            unsigned long long b2[4], a2;
            pack2(b2[0], bL.x, bL.y);
            pack2(b2[1], bL.z, bL.w);
            pack2(b2[2], bH.x, bH.y);
            pack2(b2[3], bH.z, bH.w);
            float arr[8] = {aL.x, aL.y, aL.z, aL.w, aH.x, aH.y, aH.z, aH.w};
#pragma unroll
            for (int i = 0; i < 8; ++i) {
                splat2(a2, arr[i]);
#pragma unroll
                for (int j = 0; j < 4; ++j) ffma2(acc2[i][j], a2, b2[j]);
            }
        }
        __syncthreads();
    }

    float bl[8];
#pragma unroll
    for (int c = 0; c < 4; ++c) {
        int coL = n0 + tx * 4 + c;
        int coH = n0 + 64 + tx * 4 + c;
        bl[c]     = (COUT % 128 == 0 || coL < COUT) ? bias[coL] : 0.0f;
        bl[4 + c] = (COUT % 128 == 0 || coH < COUT) ? bias[coH] : 0.0f;
    }
    float local = 0.0f;
#pragma unroll
    for (int i = 0; i < 8; ++i) {
        int m = (i < 4) ? (ty * 4 + i) : (64 + ty * 4 + (i - 4));
        int r = r0 + m;
        float v[8];
        unpack2(v[0], v[1], acc2[i][0]);
        unpack2(v[2], v[3], acc2[i][1]);
        unpack2(v[4], v[5], acc2[i][2]);
        unpack2(v[6], v[7], acc2[i][3]);
#pragma unroll
        for (int hf = 0; hf < 2; ++hf) {
            int cobase = n0 + 64 * hf + tx * 4;
            float g0 = gelu_exact(v[4 * hf + 0] + bl[4 * hf + 0]);
            float g1 = gelu_exact(v[4 * hf + 1] + bl[4 * hf + 1]);
            float g2 = gelu_exact(v[4 * hf + 2] + bl[4 * hf + 2]);
            float g3 = gelu_exact(v[4 * hf + 3] + bl[4 * hf + 3]);
            if (FUSE_MSE) {
                float gg[4] = {g0, g1, g2, g3};
#pragma unroll
                for (int c = 0; c < 4; ++c) {
                    int co = cobase + c;
                    if (co < COUT) {
                        float d = xref[(size_t)r * COUT + co] - gg[c];
                        local += d * d;
                    }
                }
            } else if (COUT % 128 == 0) {
                *(float4*)&out[(size_t)r * COUT + cobase] = make_float4(g0, g1, g2, g3);
            } else {
                float gg[4] = {g0, g1, g2, g3};
#pragma unroll
                for (int c = 0; c < 4; ++c) {
                    int co = cobase + c;
                    if (co < COUT) out[(size_t)r * COUT + co] = gg[c];
                }
            }
        }
    }
    if (FUSE_MSE) {
        __shared__ float red[256];
        red[tid] = local;
        __syncthreads();
        for (int s = 128; s > 0; s >>= 1) {
            if (tid < s) red[tid] += red[tid + s];
            __syncthreads();
        }
        if (tid == 0) atomicAdd(&g_acc[1], red[0]);
    }
}

// ---------------- bf16 split helper ----------------
__device__ __forceinline__ void cvt_split2(__nv_bfloat16* hi, __nv_bfloat16* lo,
                                           float x, float y) {
    __nv_bfloat16 xh = __float2bfloat16(x);
    __nv_bfloat16 yh = __float2bfloat16(y);
    __nv_bfloat16 xl = __float2bfloat16(x - __bfloat162float(xh));
    __nv_bfloat16 yl = __float2bfloat16(y - __bfloat162float(yh));
    *(__nv_bfloat162*)hi = __halves2bfloat162(xh, yh);
    *(__nv_bfloat162*)lo = __halves2bfloat162(xl, yl);
}

// ---------------- conv_mma: 2-pass bf16 mma conv (A split, B bf16) ---------
template<int CIN, int COUT, int NBPAD, bool FUSE_MSE>
__global__ void __launch_bounds__(256, 2) conv_mma(
    const float* __restrict__ in, const float* __restrict__ wTT,
    const float* __restrict__ bias, float* __restrict__ out,
    const float* __restrict__ xref)
{
    __shared__ __align__(16) __nv_bfloat16 sAh[2][128][24];
    __shared__ __align__(16) __nv_bfloat16 sAl[2][128][24];
    __shared__ __align__(16) __nv_bfloat16 sBh[2][64][24];
    constexpr int NC = CIN / 16;
    constexpr int NS = 3 * NC;

    const int tid = threadIdx.x;
    const int w = tid >> 5, l = tid & 31;
    const int r0 = blockIdx.x * 128;
    const int n0 = blockIdx.y * 64;

    const int arow = tid >> 1;
    const int adh  = (tid & 1) * 8;
    const int aRow = r0 + arow;
    const int tt = aRow & (TT - 1);
    const int brow = tid >> 2;
    const int bdq  = (tid & 3) * 4;
    const float* bBase = wTT + ((size_t)(n0 + brow)) * CIN + bdq;

    float acc[8][4];
#pragma unroll
    for (int j = 0; j < 8; ++j)
#pragma unroll
        for (int c = 0; c < 4; ++c) acc[j][c] = 0.0f;

    float4 a0v, a1v, bv;
    auto LDG = [&](int s) {
        const int tap = s / NC;
        const int ccc = (s - tap * NC) * 16;
        const int st = tt + tap - 1;
        if (st >= 0 && st < TT) {
            const float* ap = in + (size_t)(aRow + tap - 1) * CIN + ccc + adh;
            a0v = *(const float4*)(ap);
            a1v = *(const float4*)(ap + 4);
        } else {
            a0v = make_float4(0.f, 0.f, 0.f, 0.f);
            a1v = a0v;
        }
        bv = *(const float4*)(bBase + (size_t)tap * NBPAD * CIN + ccc);
    };
    auto CVTSTS = [&](int p) {
        cvt_split2(&sAh[p][arow][adh + 0], &sAl[p][arow][adh + 0], a0v.x, a0v.y);
        cvt_split2(&sAh[p][arow][adh + 2], &sAl[p][arow][adh + 2], a0v.z, a0v.w);
        cvt_split2(&sAh[p][arow][adh + 4], &sAl[p][arow][adh + 4], a1v.x, a1v.y);
        cvt_split2(&sAh[p][arow][adh + 6], &sAl[p][arow][adh + 6], a1v.z, a1v.w);
        *(__nv_bfloat162*)&sBh[p][brow][bdq + 0] =
            __halves2bfloat162(__float2bfloat16(bv.x), __float2bfloat16(bv.y));
        *(__nv_bfloat162*)&sBh[p][brow][bdq + 2] =
            __halves2bfloat162(__float2bfloat16(bv.z), __float2bfloat16(bv.w));
    };

    const int arl = l & 15, ach = (l >> 4) * 8;
    const int bg = l >> 3;
    const int bn = ((bg >= 2) ? 8 : 0) + (l & 7);
    const int bkoff = (bg & 1) * 8;

    LDG(0); CVTSTS(0);
    __syncthreads();

    for (int s = 0; s < NS; ++s) {
        const int p = s & 1;
        if (s + 1 < NS) LDG(s + 1);

        uint32_t ah[4], al[4];
        LDSM_X4(ah[0], ah[1], ah[2], ah[3], smem_u32(&sAh[p][w * 16 + arl][ach]));
        LDSM_X4(al[0], al[1], al[2], al[3], smem_u32(&sAl[p][w * 16 + arl][ach]));
        uint32_t bh[4][4];
#pragma unroll
        for (int nb = 0; nb < 4; ++nb)
            LDSM_X4(bh[nb][0], bh[nb][1], bh[nb][2], bh[nb][3],
                    smem_u32(&sBh[p][nb * 16 + bn][bkoff]));
#pragma unroll
        for (int nb = 0; nb < 4; ++nb) {
#pragma unroll
            for (int h = 0; h < 2; ++h) {
                const int j = nb * 2 + h;
                MMA_BF16(acc[j], ah, bh[nb][2 * h], bh[nb][2 * h + 1]);
                MMA_BF16(acc[j], al, bh[nb][2 * h], bh[nb][2 * h + 1]);
            }
        }
        if (s + 1 < NS) CVTSTS(p ^ 1);
        __syncthreads();
    }

    const int row0 = r0 + w * 16 + (l >> 2);
    const int col0 = n0 + 2 * (l & 3);
    float local = 0.0f;
#pragma unroll
    for (int j = 0; j < 8; ++j) {
        int c0 = col0 + j * 8;
        float b0 = 0.f, b1 = 0.f;
        if (COUT % 64 == 0 || c0 < COUT)     b0 = bias[c0];
        if (COUT % 64 == 0 || c0 + 1 < COUT) b1 = bias[c0 + 1];
        float g00 = gelu_exact(acc[j][0] + b0);
        float g01 = gelu_exact(acc[j][1] + b1);
        float g10 = gelu_exact(acc[j][2] + b0);
        float g11 = gelu_exact(acc[j][3] + b1);
        if (FUSE_MSE) {
            if (c0 < COUT) {
                float d0 = xref[(size_t)row0 * COUT + c0] - g00;
                float d1 = xref[(size_t)(row0 + 8) * COUT + c0] - g10;
                local += d0 * d0 + d1 * d1;
            }
            if (c0 + 1 < COUT) {
                float d0 = xref[(size_t)row0 * COUT + c0 + 1] - g01;
                float d1 = xref[(size_t)(row0 + 8) * COUT + c0 + 1] - g11;
                local += d0 * d0 + d1 * d1;
            }
        } else {
            *(float2*)&out[(size_t)row0 * COUT + c0] = make_float2(g00, g01);
            *(float2*)&out[(size_t)(row0 + 8) * COUT + c0] = make_float2(g10, g11);
        }
    }
    if (FUSE_MSE) {
        __shared__ float red[256];
        red[tid] = local;
        __syncthreads();
        for (int ss = 128; ss > 0; ss >>= 1) {
            if (tid < ss) red[tid] += red[tid + ss];
            __syncthreads();
        }
        if (tid == 0) atomicAdd(&g_acc[1], red[0]);
    }
}

// ---------------- shared pipelined-GEMM body (generalized B) --------------
#define GEMM_BODY(AROW_EXPR, BBASE, BSTRIDE)                                   \
    const int sm  = tid >> 1;                                                  \
    const int skq = tid & 1;                                                   \
    const int arow = (AROW_EXPR);                                              \
    const float* aptr = Abase + (size_t)arow * DD + 8 * skq;                   \
    const int bk  = tid >> 4;                                                  \
    const int bn4 = (tid & 15) * 4;                                            \
    const float* bbase = (BBASE) + (size_t)bk * (BSTRIDE) + k0;                \
    unsigned long long acc2[8][4];                                             \
    _Pragma("unroll")                                                          \
    for (int i = 0; i < 8; ++i)                                                \
        _Pragma("unroll")                                                      \
        for (int j = 0; j < 4; ++j) acc2[i][j] = 0ull;                         \
    float4 av0, av1, bv0, bv1;                                                 \
    auto LOAD = [&](int cc) {                                                  \
        av0 = *(const float4*)(aptr + cc);                                     \
        av1 = *(const float4*)(aptr + cc + 4);                                 \
        const float* bp = bbase + (size_t)cc * (BSTRIDE);                      \
        bv0 = *(const float4*)(bp + bn4);                                      \
        bv1 = *(const float4*)(bp + 64 + bn4);                                 \
    };                                                                         \
    auto STORE = [&](int p) {                                                  \
        As[p][8 * skq + 0][sm] = av0.x;                                        \
        As[p][8 * skq + 1][sm] = av0.y;                                        \
        As[p][8 * skq + 2][sm] = av0.z;                                        \
        As[p][8 * skq + 3][sm] = av0.w;                                        \
        As[p][8 * skq + 4][sm] = av1.x;                                        \
        As[p][8 * skq + 5][sm] = av1.y;                                        \
        As[p][8 * skq + 6][sm] = av1.z;                                        \
        As[p][8 * skq + 7][sm] = av1.w;                                        \
        *(float4*)&Bs[p][bk][bn4]      = bv0;                                  \
        *(float4*)&Bs[p][bk][64 + bn4] = bv1;                                  \
    };                                                                         \
    LOAD(0); STORE(0);                                                         \
    LOAD(16);                                                                  \
    __syncthreads();                                                           \
    for (int ch = 0; ch < 32; ++ch) {                                          \
        const int p = ch & 1;                                                  \
        if (ch + 1 < 32) STORE(p ^ 1);                                         \
        if (ch + 2 < 32) LOAD((ch + 2) * 16);                                  \
        _Pragma("unroll")                                                      \
        for (int kk = 0; kk < 16; ++kk) {                                      \
            float4 aL = *(const float4*)&As[p][kk][ty * 4];                    \
            float4 aH = *(const float4*)&As[p][kk][64 + ty * 4];               \
            float4 bL = *(const float4*)&Bs[p][kk][tx * 4];                    \
            float4 bH = *(const float4*)&Bs[p][kk][64 + tx * 4];               \
            unsigned long long b2[4], a2;                                      \
            pack2(b2[0], bL.x, bL.y);                                          \
            pack2(b2[1], bL.z, bL.w);                                          \
            pack2(b2[2], bH.x, bH.y);                                          \
            pack2(b2[3], bH.z, bH.w);                                          \
            float arr[8] = {aL.x, aL.y, aL.z, aL.w, aH.x, aH.y, aH.z, aH.w};   \
            _Pragma("unroll")                                                  \
            for (int i = 0; i < 8; ++i) {                                      \
                splat2(a2, arr[i]);                                            \
                _Pragma("unroll")                                              \
                for (int j = 0; j < 4; ++j) ffma2(acc2[i][j], a2, b2[j]);      \
            }                                                                  \
        }                                                                      \
        __syncthreads();                                                       \
    }

// ---------------- stage-0 GEMM via 2-pass bf16 mma -------------------------
__global__ void __launch_bounds__(256, 2) vq_gemm_mma(
    const float* __restrict__ zin, const float* __restrict__ cb)
{
    __shared__ __align__(16) __nv_bfloat16 sAh[2][128][24];
    __shared__ __align__(16) __nv_bfloat16 sAl[2][128][24];
    __shared__ __align__(16) __nv_bfloat16 sBh[2][64][24];

    const int tid = threadIdx.x;
    const int w = tid >> 5, l = tid & 31;
    const int r0 = blockIdx.x * 128;
    const int k0 = blockIdx.y * 64;

    const int arow = tid >> 1;
    const int adh  = (tid & 1) * 8;
    const float* aP = zin + (size_t)(r0 + arow) * DD + adh;
    const int brow = tid >> 2;
    const int bdq  = (tid & 3) * 4;
    const float* bP = cb + (size_t)(k0 + brow) * DD + bdq;

    float acc[8][4];
#pragma unroll
    for (int j = 0; j < 8; ++j)
#pragma unroll
        for (int c = 0; c < 4; ++c) acc[j][c] = 0.0f;

    float4 a0v, a1v, bv;
    auto LDG = [&](int ks) {
        a0v = *(const float4*)(aP + ks * 16);
        a1v = *(const float4*)(aP + ks * 16 + 4);
        bv  = *(const float4*)(bP + ks * 16);
    };
    auto CVTSTS = [&](int p) {
        cvt_split2(&sAh[p][arow][adh + 0], &sAl[p][arow][adh + 0], a0v.x, a0v.y);
        cvt_split2(&sAh[p][arow][adh + 2], &sAl[p][arow][adh + 2], a0v.z, a0v.w);
        cvt_split2(&sAh[p][arow][adh + 4], &sAl[p][arow][adh + 4], a1v.x, a1v.y);
        cvt_split2(&sAh[p][arow][adh + 6], &sAl[p][arow][adh + 6], a1v.z, a1v.w);
        *(__nv_bfloat162*)&sBh[p][brow][bdq + 0] =
            __halves2bfloat162(__float2bfloat16(bv.x), __float2bfloat16(bv.y));
        *(__nv_bfloat162*)&sBh[p][brow][bdq + 2] =
            __halves2bfloat162(__float2bfloat16(bv.z), __float2bfloat16(bv.w));
    };

    const int arl = l & 15, ach = (l >> 4) * 8;
    const int bg = l >> 3;
    const int bn = ((bg >= 2) ? 8 : 0) + (l & 7);
    const int bkoff = (bg & 1) * 8;

    LDG(0); CVTSTS(0);
    __syncthreads();

    for (int ks = 0; ks < 32; ++ks) {
        const int p = ks & 1;
        if (ks + 1 < 32) LDG(ks + 1);

        uint32_t ah[4], al[4];
        LDSM_X4(ah[0], ah[1], ah[2], ah[3], smem_u32(&sAh[p][w * 16 + arl][ach]));
        LDSM_X4(al[0], al[1], al[2], al[3], smem_u32(&sAl[p][w * 16 + arl][ach]));
        uint32_t bh[4][4];
#pragma unroll
        for (int nb = 0; nb < 4; ++nb)
            LDSM_X4(bh[nb][0], bh[nb][1], bh[nb][2], bh[nb][3],
                    smem_u32(&sBh[p][nb * 16 + bn][bkoff]));
#pragma unroll
        for (int nb = 0; nb < 4; ++nb) {
#pragma unroll
            for (int h = 0; h < 2; ++h) {
                const int j = nb * 2 + h;
                MMA_BF16(acc[j], ah, bh[nb][2 * h], bh[nb][2 * h + 1]);
                MMA_BF16(acc[j], al, bh[nb][2 * h], bh[nb][2 * h + 1]);
            }
        }
        if (ks + 1 < 32) CVTSTS(p ^ 1);
        __syncthreads();
    }

    const int row0 = r0 + w * 16 + (l >> 2);
    const int col0 = k0 + 2 * (l & 3);
#pragma unroll
    for (int j = 0; j < 8; ++j) {
        *(float2*)&g_dist[(size_t)row0 * KK + col0 + j * 8] =
            make_float2(acc[j][0], acc[j][1]);
        *(float2*)&g_dist[(size_t)(row0 + 8) * KK + col0 + j * 8] =
            make_float2(acc[j][2], acc[j][3]);
    }
}

// ---------------- Gram GEMM: G = cb · cbT + csq = diag(G) ------------------
__global__ void __launch_bounds__(256, 2) gram_gemm(const float* __restrict__ cb) {
    __shared__ __align__(16) float As[2][16][SAS];
    __shared__ __align__(16) float Bs[2][16][SAS];
    const int tid = threadIdx.x;
    const int tx = tid & 15, ty = tid >> 4;
    const int r0 = blockIdx.x * 128;
    const int k0 = blockIdx.y * 128;
    const float* Abase = cb;
    GEMM_BODY(r0 + (tid >> 1), g_cbT, KK)

#pragma unroll
    for (int i = 0; i < 8; ++i) {
        int m = (i < 4) ? (ty * 4 + i) : (64 + ty * 4 + (i - 4));
        int row = r0 + m;
        float d0, d1, d2, d3;
        unpack2(d0, d1, acc2[i][0]);
        unpack2(d2, d3, acc2[i][1]);
        *(float4*)&g_G[(size_t)row * KK + k0 + tx * 4] = make_float4(d0, d1, d2, d3);
        if (r0 == k0) {
            int c0 = k0 + tx * 4;
            if (row >= c0 && row < c0 + 4) {
                float dd[4] = {d0, d1, d2, d3};
                g_csq[row] = dd[row - c0];
            }
        }
        unpack2(d0, d1, acc2[i][2]);
        unpack2(d2, d3, acc2[i][3]);
        *(float4*)&g_G[(size_t)row * KK + k0 + 64 + tx * 4] = make_float4(d0, d1, d2, d3);
        if (r0 == k0) {
            int c1 = k0 + 64 + tx * 4;
            if (row >= c1 && row < c1 + 4) {
                float dd[4] = {d0, d1, d2, d3};
                g_csq[row] = dd[row - c1];
            }
        }
    }
}

// ---------------- U GEMM: U[tap] = cb · W1_tap^T  (grid 8 x 2 x 3) ---------
__global__ void __launch_bounds__(256, 2) u_gemm(const float* __restrict__ cb) {
    __shared__ __align__(16) float As[2][16][SAS];
    __shared__ __align__(16) float Bs[2][16][SAS];
    const int tid = threadIdx.x;
    const int tx = tid & 15, ty = tid >> 4;
    const int r0 = blockIdx.x * 128;
    const int k0 = blockIdx.y * 128;
    const int tap = blockIdx.z;
    const float* Abase = cb;
    const float* wt3 = g_wT + WT_O3 + (size_t)tap * 512 * 256;
    GEMM_BODY(r0 + (tid >> 1), wt3, 256)

#pragma unroll
    for (int i = 0; i < 8; ++i) {
        int m = (i < 4) ? (ty * 4 + i) : (64 + ty * 4 + (i - 4));
        int row = r0 + m;
        float* urow = &g_U[((size_t)tap * KK + row) * 256 + k0];
        float d0, d1, d2, d3;
        unpack2(d0, d1, acc2[i][0]);
        unpack2(d2, d3, acc2[i][1]);
        *(float4*)(urow + tx * 4) = make_float4(d0, d1, d2, d3);
        unpack2(d0, d1, acc2[i][2]);
        unpack2(d2, d3, acc2[i][3]);
        *(float4*)(urow + 64 + tx * 4) = make_float4(d0, d1, d2, d3);
    }
}

// ---------------- init_small ----------------
__global__ void init_small() {
    int tid = threadIdx.x;  // 32
    if (tid < 8) {
        unsigned a, b;
        tf2x32(0u, 42u, 0u, (unsigned)tid, a, b);
        g_fk[2 * tid] = a;
        g_fk[2 * tid + 1] = b;
    }
    if (tid < 2) g_acc[tid] = 0.0f;
    if (tid == 0) {
        float ghi = gumbel_from_bits(0xFFFFFFFFu);
        float glo = gumbel_from_bits(0u);
        g_window = (ghi - glo) + 0.5f;
    }
}

// ---------------- pick: rn2 + all 8 VQ stages per row -> g_sel -------------
__global__ void __launch_bounds__(256) vq_pick() {
    const int bt = blockIdx.x;
    const int tid = threadIdx.x;
    __shared__ unsigned sMaxU;
    __shared__ unsigned long long sBest;
    __shared__ float sDotSel;
    __shared__ int sSel[8];
    __shared__ float red[256];

    if (tid == 0) { sMaxU = 0u; sBest = 0ull; }

    {
        float z0 = g_res[(size_t)bt * DD + tid];
        float z1 = g_res[(size_t)bt * DD + tid + 256];
        red[tid] = z0 * z0 + z1 * z1;
    }

    float d[4], cs[4], s[4];
    const float* drow = &g_dist[(size_t)bt * KK];
#pragma unroll
    for (int j = 0; j < 4; ++j) {
        d[j] = drow[tid + 256 * j];
        cs[j] = g_csq[tid + 256 * j];
        s[j] = fmaf(20.0f, d[j], -10.0f * cs[j]);
    }
    __syncthreads();
    for (int ss = 128; ss > 0; ss >>= 1) {
        if (tid < ss) red[tid] += red[tid + ss];
        __syncthreads();
    }
    const float win = g_window;
    const unsigned btL = (bt < 8192) ? (unsigned)bt : (unsigned)(bt - 8192);
    const bool hi = (bt >= 8192);
    float rn2 = (tid == 0) ? red[0] : 0.0f;
    float commit = 0.0f;

    for (int i = 0; i < 8; ++i) {
        float lm = fmaxf(fmaxf(s[0], s[1]), fmaxf(s[2], s[3]));
#pragma unroll
        for (int off = 16; off > 0; off >>= 1)
            lm = fmaxf(lm, __shfl_xor_sync(0xffffffffu, lm, off));
        if ((tid & 31) == 0) atomicMax(&sMaxU, fmap(lm));
        __syncthreads();
        const float tau = unfmap(sMaxU) - win;

        const unsigned fk0 = g_fk[2 * i], fk1 = g_fk[2 * i + 1];
#pragma unroll
        for (int j = 0; j < 4; ++j) {
            if (s[j] >= tau) {
                unsigned k = (unsigned)(tid + 256 * j);
                unsigned n = btL * 1024u + k;
                unsigned b0, b1;
                tf2x32(fk0, fk1, n, n + HALF_N, b0, b1);
                float g = gumbel_from_bits(hi ? b1 : b0);
                float sc = s[j] + g;
                unsigned long long cand =
                    ((unsigned long long)fmap(sc) << 32) | (unsigned long long)(~k);
                atomicMax(&sBest, cand);
            }
        }
        __syncthreads();
        const unsigned sel = ~(unsigned)(sBest & 0xffffffffull);
        if (tid == (int)(sel & 255u)) sDotSel = d[sel >> 8];
        __syncthreads();
        if (tid == 0) {
            float rn2n = rn2 - 2.0f * sDotSel + g_csq[sel];
            commit += rn2n;
            rn2 = rn2n;
            sSel[i] = (int)sel;
            sMaxU = 0u;
            sBest = 0ull;
        }
        if (i < 7) {
            const float* grow = &g_G[(size_t)sel * KK];
#pragma unroll
            for (int j = 0; j < 4; ++j) {
                d[j] -= grow[tid + 256 * j];
                s[j] = fmaf(20.0f, d[j], -10.0f * cs[j]);
            }
        }
        __syncthreads();
    }

    if (tid < 8) g_sel[bt * 8 + tid] = sSel[tid];
    if (tid == 0) atomicAdd(&g_acc[0], commit);
}

// ---------------- dec1 gather: h1[bt] = gelu(bias + sum U rows) ------------
__global__ void __launch_bounds__(256) dec1_gather(const float* __restrict__ bias) {
    const int bt = blockIdx.x;
    const int c = threadIdx.x;
    __shared__ int sIdx[24];

    if (c < 24) {
        int tap = c >> 3, i = c & 7;
        int t = bt & (TT - 1);
        int st = t + tap - 1;
        int idx = -1;
        if (st >= 0 && st < TT)
            idx = tap * KK + g_sel[(bt + tap - 1) * 8 + i];
        sIdx[c] = idx;
    }
    __syncthreads();

    float acc = bias[c];
#pragma unroll
    for (int j = 0; j < 24; ++j) {
        int idx = sIdx[j];
        if (idx >= 0) acc += g_U[(size_t)idx * 256 + c];
    }
    g_h1[(size_t)bt * 256 + c] = gelu_exact(acc);
}

__global__ void finalize_k(float* __restrict__ out) {
    out[0] = g_acc[1] * (1.0f / 1638400.0f)
           + g_acc[0] * (1.0f / 67108864.0f);
}

// ---------------- streams/events (created once, pre-baseline) --------------
struct SideStream {
    cudaStream_t s;
    cudaEvent_t fork, wtev, join1, join2;
    SideStream() {
        cudaStreamCreateWithFlags(&s, cudaStreamNonBlocking);
        cudaEventCreateWithFlags(&fork, cudaEventDisableTiming);
        cudaEventCreateWithFlags(&wtev, cudaEventDisableTiming);
        cudaEventCreateWithFlags(&join1, cudaEventDisableTiming);
        cudaEventCreateWithFlags(&join2, cudaEventDisableTiming);
    }
};
static SideStream g_ss;

// ---------------- host launcher (graph-capturable, alloc-free) -------------
extern "C" void kernel_launch(void* const* d_in, const int* in_sizes, int n_in,
                              void* d_out, int out_size) {
    const float* x   = (const float*)d_in[0];
    const float* ew1 = (const float*)d_in[1];
    const float* eb1 = (const float*)d_in[2];
    const float* ew2 = (const float*)d_in[3];
    const float* eb2 = (const float*)d_in[4];
    const float* cb  = (const float*)d_in[5];
    const float* dw1 = (const float*)d_in[6];
    const float* db1 = (const float*)d_in[7];
    const float* dw2 = (const float*)d_in[8];
    const float* db2 = (const float*)d_in[9];
    float* out = (float*)d_out;

    float *h1, *res, *wT, *wTT;
    cudaGetSymbolAddress((void**)&h1,  g_h1);
    cudaGetSymbolAddress((void**)&res, g_res);
    cudaGetSymbolAddress((void**)&wT,  g_wT);
    cudaGetSymbolAddress((void**)&wTT, g_wTT);

    // fork side branch: cbT -> Gram(+csq) -> init_small
    cudaEventRecord(g_ss.fork, 0);
    cudaStreamWaitEvent(g_ss.s, g_ss.fork, 0);
    transpose_cb<<<dim3(KK / 32, DD / 32), dim3(32, 8), 0, g_ss.s>>>(cb);
    gram_gemm<<<dim3(8, 8), 256, 0, g_ss.s>>>(cb);
    init_small<<<1, 32, 0, g_ss.s>>>();
    cudaEventRecord(g_ss.join1, g_ss.s);

    // main branch: weights (both layouts) -> encoder
    transpose_w_all<<<(WT_END + WTT_END + 255) / 256, 256>>>(ew1, ew2, dw1, dw2);
    cudaEventRecord(g_ss.wtev, 0);

    // side: U = cb · dec_w1^T per tap (needs wT3) — overlaps encoder convs
    cudaStreamWaitEvent(g_ss.s, g_ss.wtev, 0);
    u_gemm<<<dim3(8, 2, 3), 256, 0, g_ss.s>>>(cb);
    cudaEventRecord(g_ss.join2, g_ss.s);

    conv3f<100, 256, 256, false><<<dim3(128, 2), 256>>>(x, wT + WT_O1, eb1, h1, nullptr);
    conv_mma<256, 512, 512, false><<<dim3(128, 8), 256>>>(h1, wTT + WTT_O2, eb2, res, nullptr);

    // join: vq needs cbT / G / csq / fk / window
    cudaStreamWaitEvent(0, g_ss.join1, 0);
    vq_gemm_mma<<<dim3(128, 16), 256>>>(res, cb);
    vq_pick<<<BT, 256>>>();

    // decoder: gathered dec1 (needs U), then dec2 mma conv with fused MSE
    cudaStreamWaitEvent(0, g_ss.join2, 0);
    dec1_gather<<<BT, 256>>>(db1);
    conv_mma<256, 100, 128, true><<<dim3(128, 2), 256>>>(h1, wTT + WTT_O4, db2, nullptr, x);

    finalize_k<<<1, 1>>>(out);
}

// round 17
// speedup vs baseline: 1.3209x; 1.1174x over previous
#include <cuda_runtime.h>
#include <cuda_bf16.h>
#include <cstdint>

#define TT 2048
#define BT 16384
#define DD 512
#define KK 1024
#define HALF_N 8388608u   // BT*KK/2

// ---------------- scratch (static device allocations only) ----------------
__device__ float g_xpad[BT * 112];        // zero-padded input (7MB)
__device__ float g_h1[BT * 256];
__device__ float g_res[BT * DD];          // encoder output z
__device__ float g_cbT[DD * KK];          // codebook transposed [d][k]
__device__ float g_dist[BT * KK];         // dot products <z, c_k>  (64MB)
__device__ float g_G[KK * KK];            // Gram matrix cb·cbT     (4MB)
__device__ float g_csq[KK];               // = diag(G)
__device__ float g_wT[393216];            // dec1 [tap][ci][co] fp32 (1.5MB)
__device__ float g_wTT[577536];           // [tap][co][ci] for mma convs
__device__ float g_U[3 * KK * 256];       // U[tap][k][co] = cb·W1_tap^T (3MB)
__device__ int   g_sel[BT * 8];
__device__ unsigned g_fk[16];
__device__ float g_window;
__device__ float g_acc[2];   // [0]=commit sum, [1]=mse sum

#define WTT_O1 0
#define WTT_O2 86016
#define WTT_O4 479232
#define WTT_END 577536
#define WT3_END 393216

// ---------------- packed f32x2 helpers (for fp32 GEMM_BODY kernels) -------
__device__ __forceinline__ void splat2(unsigned long long& d, float a) {
    asm("mov.b64 %0, {%1, %1};" : "=l"(d) : "f"(a));
}
__device__ __forceinline__ void pack2(unsigned long long& d, float a, float b) {
    asm("mov.b64 %0, {%1, %2};" : "=l"(d) : "f"(a), "f"(b));
}
__device__ __forceinline__ void unpack2(float& a, float& b, unsigned long long d) {
    asm("mov.b64 {%0, %1}, %2;" : "=f"(a), "=f"(b) : "l"(d));
}
__device__ __forceinline__ void ffma2(unsigned long long& acc,
                                      unsigned long long a, unsigned long long b) {
    asm("fma.rn.f32x2 %0, %1, %2, %0;" : "+l"(acc) : "l"(a), "l"(b));
}

// ---------------- mma.sync / ldmatrix helpers ----------------
__device__ __forceinline__ uint32_t smem_u32(const void* p) {
    uint32_t a;
    asm("{ .reg .u64 t; cvta.to.shared.u64 t, %1; cvt.u32.u64 %0, t; }"
        : "=r"(a) : "l"(p));
    return a;
}
#define LDSM_X4(r0, r1, r2, r3, addr) \
    asm volatile("ldmatrix.sync.aligned.m8n8.x4.shared.b16 {%0,%1,%2,%3}, [%4];" \
        : "=r"(r0), "=r"(r1), "=r"(r2), "=r"(r3) : "r"(addr))
#define MMA_BF16(d, a, b0, b1) \
    asm volatile("mma.sync.aligned.m16n8k16.row.col.f32.bf16.bf16.f32 " \
        "{%0,%1,%2,%3}, {%4,%5,%6,%7}, {%8,%9}, {%0,%1,%2,%3};" \
        : "+f"((d)[0]), "+f"((d)[1]), "+f"((d)[2]), "+f"((d)[3]) \
        : "r"((a)[0]), "r"((a)[1]), "r"((a)[2]), "r"((a)[3]), "r"(b0), "r"(b1))

// ---------------- JAX threefry2x32 (exact) ----------------
__host__ __device__ inline void tf2x32(unsigned k0, unsigned k1,
                                       unsigned x0, unsigned x1,
                                       unsigned& o0, unsigned& o1) {
    unsigned ks2 = k0 ^ k1 ^ 0x1BD11BDAu;
    x0 += k0; x1 += k1;
#define TF_RND(r) { x0 += x1; x1 = (x1 << (r)) | (x1 >> (32 - (r))); x1 ^= x0; }
    TF_RND(13) TF_RND(15) TF_RND(26) TF_RND(6)
    x0 += k1;  x1 += ks2 + 1u;
    TF_RND(17) TF_RND(29) TF_RND(16) TF_RND(24)
    x0 += ks2; x1 += k0 + 2u;
    TF_RND(13) TF_RND(15) TF_RND(26) TF_RND(6)
    x0 += k0;  x1 += k1 + 3u;
    TF_RND(17) TF_RND(29) TF_RND(16) TF_RND(24)
    x0 += k1;  x1 += ks2 + 4u;
    TF_RND(13) TF_RND(15) TF_RND(26) TF_RND(6)
    x0 += ks2; x1 += k0 + 5u;
#undef TF_RND
    o0 = x0; o1 = x1;
}

__device__ inline float gumbel_from_bits(unsigned bits) {
    float f = __uint_as_float((bits >> 9) | 0x3f800000u) - 1.0f;
    float u = (f == 0.0f) ? 1.17549435e-38f : f;
    return -__logf(-__logf(u));
}

__device__ inline unsigned fmap(float f) {
    unsigned u = __float_as_uint(f);
    return (u & 0x80000000u) ? ~u : (u | 0x80000000u);
}
__device__ inline float unfmap(unsigned u) {
    unsigned v = (u & 0x80000000u) ? (u ^ 0x80000000u) : ~u;
    return __uint_as_float(v);
}

__device__ inline float gelu_exact(float v) {
    return 0.5f * v * (1.0f + erff(v * 0.7071067811865476f));
}

__device__ __forceinline__ void cvt_split2(__nv_bfloat16* hi, __nv_bfloat16* lo,
                                           float x, float y) {
    __nv_bfloat16 xh = __float2bfloat16(x);
    __nv_bfloat16 yh = __float2bfloat16(y);
    __nv_bfloat16 xl = __float2bfloat16(x - __bfloat162float(xh));
    __nv_bfloat16 yl = __float2bfloat16(y - __bfloat162float(yh));
    *(__nv_bfloat162*)hi = __halves2bfloat162(xh, yh);
    *(__nv_bfloat162*)lo = __halves2bfloat162(xl, yl);
}

// ---------------- x pad: g_xpad[r][ci] = (ci<100) ? x[r][ci] : 0 -----------
__global__ void pad_x(const float* __restrict__ x) {
    int i = blockIdx.x * 256 + threadIdx.x;
    if (i >= BT * 112) return;
    int ci = i % 112, r = i / 112;
    g_xpad[i] = (ci < 100) ? x[r * 100 + ci] : 0.0f;
}

// ---------------- codebook transpose ----------------
__global__ void transpose_cb(const float* __restrict__ cb) {
    __shared__ float t[32][33];
    int k0 = blockIdx.x * 32;
    int d0 = blockIdx.y * 32;
    int tx = threadIdx.x, ty = threadIdx.y;  // 32 x 8
    for (int l = 0; l < 32; l += 8)
        t[ty + l][tx] = cb[(k0 + ty + l) * DD + d0 + tx];
    __syncthreads();
    for (int l = 0; l < 32; l += 8)
        g_cbT[(d0 + ty + l) * KK + k0 + tx] = t[tx][ty + l];
}

// ---------------- merged weight transpose -------------------
__device__ __forceinline__ void wtt_range(int local, const float* __restrict__ w,
                                          int CINP, int CINS, int COUT, int ROWS,
                                          float* __restrict__ dst) {
    int ci = local % CINP;
    int rest = local / CINP;
    int co = rest % ROWS;
    int tap = rest / ROWS;
    float v = 0.0f;
    if (ci < CINS && co < COUT)
        v = w[((size_t)co * CINS + ci) * 3 + tap];
    dst[local] = v;
}
__global__ void transpose_w_all(const float* __restrict__ w1, const float* __restrict__ w2,
                                const float* __restrict__ w3, const float* __restrict__ w4) {
    int idx = blockIdx.x * 256 + threadIdx.x;
    if (idx < WT3_END) {
        // dec1 [tap][ci][co] fp32 for u_gemm
        int co = idx % 256;
        int rest = idx / 256;
        int ci = rest % 512;
        int tap = rest / 512;
        g_wT[idx] = w3[((size_t)co * 512 + ci) * 3 + tap];
    }
    int j = idx;
    if (j >= WTT_END) return;
    if (j < WTT_O2)      wtt_range(j - WTT_O1, w1, 112, 100, 256, 256, g_wTT + WTT_O1);
    else if (j < WTT_O4) wtt_range(j - WTT_O2, w2, 256, 256, 512, 512, g_wTT + WTT_O2);
    else                 wtt_range(j - WTT_O4, w4, 256, 256, 100, 128, g_wTT + WTT_O4);
}

// ---------------- conv_mma8: 2-pass bf16 mma conv, N=128 tile --------------
// 8 warps, each 16 rows x 128 cols (16 fragments). B frag regs reused per nb.
// MODE 0: fp32 out. MODE 1: fused MSE vs xref (COUT maskable).
template<int CIN, int COUT, int NBPAD, int MODE>
__global__ void __launch_bounds__(256, 2) conv_mma8(
    const float* __restrict__ in, const float* __restrict__ wTT,
    const float* __restrict__ bias, float* __restrict__ out,
    const float* __restrict__ xref)
{
    __shared__ __align__(16) __nv_bfloat16 sAh[2][128][24];
    __shared__ __align__(16) __nv_bfloat16 sAl[2][128][24];
    __shared__ __align__(16) __nv_bfloat16 sBh[2][128][24];
    constexpr int NC = CIN / 16;
    constexpr int NS = 3 * NC;

    const int tid = threadIdx.x;
    const int w = tid >> 5, l = tid & 31;
    const int r0 = blockIdx.x * 128;
    const int n0 = blockIdx.y * 128;

    const int arow = tid >> 1;
    const int adh  = (tid & 1) * 8;
    const int aRow = r0 + arow;
    const int tt = aRow & (TT - 1);
    const int brow = tid >> 1;
    const int bdq  = (tid & 1) * 8;

    float acc[16][4];
#pragma unroll
    for (int j = 0; j < 16; ++j)
#pragma unroll
        for (int c = 0; c < 4; ++c) acc[j][c] = 0.0f;

    float4 a0v, a1v, b0v, b1v;
    auto LDG = [&](int s) {
        const int tap = s / NC;
        const int ccc = (s - tap * NC) * 16;
        const int st = tt + tap - 1;
        if (st >= 0 && st < TT) {
            const float* ap = in + (size_t)(aRow + tap - 1) * CIN + ccc + adh;
            a0v = *(const float4*)(ap);
            a1v = *(const float4*)(ap + 4);
        } else {
            a0v = make_float4(0.f, 0.f, 0.f, 0.f);
            a1v = a0v;
        }
        const float* bp = wTT + (size_t)(tap * NBPAD + n0 + brow) * CIN + ccc + bdq;
        b0v = *(const float4*)(bp);
        b1v = *(const float4*)(bp + 4);
    };
    auto CVTSTS = [&](int p) {
        cvt_split2(&sAh[p][arow][adh + 0], &sAl[p][arow][adh + 0], a0v.x, a0v.y);
        cvt_split2(&sAh[p][arow][adh + 2], &sAl[p][arow][adh + 2], a0v.z, a0v.w);
        cvt_split2(&sAh[p][arow][adh + 4], &sAl[p][arow][adh + 4], a1v.x, a1v.y);
        cvt_split2(&sAh[p][arow][adh + 6], &sAl[p][arow][adh + 6], a1v.z, a1v.w);
        *(__nv_bfloat162*)&sBh[p][brow][bdq + 0] =
            __halves2bfloat162(__float2bfloat16(b0v.x), __float2bfloat16(b0v.y));
        *(__nv_bfloat162*)&sBh[p][brow][bdq + 2] =
            __halves2bfloat162(__float2bfloat16(b0v.z), __float2bfloat16(b0v.w));
        *(__nv_bfloat162*)&sBh[p][brow][bdq + 4] =
            __halves2bfloat162(__float2bfloat16(b1v.x), __float2bfloat16(b1v.y));
        *(__nv_bfloat162*)&sBh[p][brow][bdq + 6] =
            __halves2bfloat162(__float2bfloat16(b1v.z), __float2bfloat16(b1v.w));
    };

    const int arl = l & 15, ach = (l >> 4) * 8;
    const int bg = l >> 3;
    const int bn = ((bg >= 2) ? 8 : 0) + (l & 7);
    const int bkoff = (bg & 1) * 8;

    LDG(0); CVTSTS(0);
    __syncthreads();

    for (int s = 0; s < NS; ++s) {
        const int p = s & 1;
        if (s + 1 < NS) LDG(s + 1);

        uint32_t ah[4], al[4];
        LDSM_X4(ah[0], ah[1], ah[2], ah[3], smem_u32(&sAh[p][w * 16 + arl][ach]));
        LDSM_X4(al[0], al[1], al[2], al[3], smem_u32(&sAl[p][w * 16 + arl][ach]));
#pragma unroll
        for (int nb = 0; nb < 8; ++nb) {
            uint32_t bh[4];
            LDSM_X4(bh[0], bh[1], bh[2], bh[3],
                    smem_u32(&sBh[p][nb * 16 + bn][bkoff]));
            MMA_BF16(acc[2 * nb],     ah, bh[0], bh[1]);
            MMA_BF16(acc[2 * nb],     al, bh[0], bh[1]);
            MMA_BF16(acc[2 * nb + 1], ah, bh[2], bh[3]);
            MMA_BF16(acc[2 * nb + 1], al, bh[2], bh[3]);
        }
        if (s + 1 < NS) CVTSTS(p ^ 1);
        __syncthreads();
    }

    const int row0 = r0 + w * 16 + (l >> 2);
    const int col0 = n0 + 2 * (l & 3);
    float local = 0.0f;
#pragma unroll
    for (int j = 0; j < 16; ++j) {
        int c0 = col0 + j * 8;
        float b0 = 0.f, b1 = 0.f;
        if (COUT % 128 == 0 || c0 < COUT)     b0 = bias[c0];
        if (COUT % 128 == 0 || c0 + 1 < COUT) b1 = bias[c0 + 1];
        float g00 = gelu_exact(acc[j][0] + b0);
        float g01 = gelu_exact(acc[j][1] + b1);
        float g10 = gelu_exact(acc[j][2] + b0);
        float g11 = gelu_exact(acc[j][3] + b1);
        if (MODE == 1) {
            if (c0 < COUT) {
                float d0 = xref[(size_t)row0 * COUT + c0] - g00;
                float d1 = xref[(size_t)(row0 + 8) * COUT + c0] - g10;
                local += d0 * d0 + d1 * d1;
            }
            if (c0 + 1 < COUT) {
                float d0 = xref[(size_t)row0 * COUT + c0 + 1] - g01;
                float d1 = xref[(size_t)(row0 + 8) * COUT + c0 + 1] - g11;
                local += d0 * d0 + d1 * d1;
            }
        } else {
            *(float2*)&out[(size_t)row0 * COUT + c0] = make_float2(g00, g01);
            *(float2*)&out[(size_t)(row0 + 8) * COUT + c0] = make_float2(g10, g11);
        }
    }
    if (MODE == 1) {
        __shared__ float red[256];
        red[tid] = local;
        __syncthreads();
        for (int ss = 128; ss > 0; ss >>= 1) {
            if (tid < ss) red[tid] += red[tid + ss];
            __syncthreads();
        }
        if (tid == 0) atomicAdd(&g_acc[1], red[0]);
    }
}

// ---------------- vq_gemm: 2-pass bf16 mma, N=128 tile ---------------------
__global__ void __launch_bounds__(256, 2) vq_gemm_mma(
    const float* __restrict__ zin, const float* __restrict__ cb)
{
    __shared__ __align__(16) __nv_bfloat16 sAh[2][128][24];
    __shared__ __align__(16) __nv_bfloat16 sAl[2][128][24];
    __shared__ __align__(16) __nv_bfloat16 sBh[2][128][24];

    const int tid = threadIdx.x;
    const int w = tid >> 5, l = tid & 31;
    const int r0 = blockIdx.x * 128;
    const int k0 = blockIdx.y * 128;

    const int arow = tid >> 1;
    const int adh  = (tid & 1) * 8;
    const float* aP = zin + (size_t)(r0 + arow) * DD + adh;
    const int brow = tid >> 1;
    const int bdq  = (tid & 1) * 8;
    const float* bP = cb + (size_t)(k0 + brow) * DD + bdq;

    float acc[16][4];
#pragma unroll
    for (int j = 0; j < 16; ++j)
#pragma unroll
        for (int c = 0; c < 4; ++c) acc[j][c] = 0.0f;

    float4 a0v, a1v, b0v, b1v;
    auto LDG = [&](int ks) {
        a0v = *(const float4*)(aP + ks * 16);
        a1v = *(const float4*)(aP + ks * 16 + 4);
        b0v = *(const float4*)(bP + ks * 16);
        b1v = *(const float4*)(bP + ks * 16 + 4);
    };
    auto CVTSTS = [&](int p) {
        cvt_split2(&sAh[p][arow][adh + 0], &sAl[p][arow][adh + 0], a0v.x, a0v.y);
        cvt_split2(&sAh[p][arow][adh + 2], &sAl[p][arow][adh + 2], a0v.z, a0v.w);
        cvt_split2(&sAh[p][arow][adh + 4], &sAl[p][arow][adh + 4], a1v.x, a1v.y);
        cvt_split2(&sAh[p][arow][adh + 6], &sAl[p][arow][adh + 6], a1v.z, a1v.w);
        *(__nv_bfloat162*)&sBh[p][brow][bdq + 0] =
            __halves2bfloat162(__float2bfloat16(b0v.x), __float2bfloat16(b0v.y));
        *(__nv_bfloat162*)&sBh[p][brow][bdq + 2] =
            __halves2bfloat162(__float2bfloat16(b0v.z), __float2bfloat16(b0v.w));
        *(__nv_bfloat162*)&sBh[p][brow][bdq + 4] =
            __halves2bfloat162(__float2bfloat16(b1v.x), __float2bfloat16(b1v.y));
        *(__nv_bfloat162*)&sBh[p][brow][bdq + 6] =
            __halves2bfloat162(__float2bfloat16(b1v.z), __float2bfloat16(b1v.w));
    };

    const int arl = l & 15, ach = (l >> 4) * 8;
    const int bg = l >> 3;
    const int bn = ((bg >= 2) ? 8 : 0) + (l & 7);
    const int bkoff = (bg & 1) * 8;

    LDG(0); CVTSTS(0);
    __syncthreads();

    for (int ks = 0; ks < 32; ++ks) {
        const int p = ks & 1;
        if (ks + 1 < 32) LDG(ks + 1);

        uint32_t ah[4], al[4];
        LDSM_X4(ah[0], ah[1], ah[2], ah[3], smem_u32(&sAh[p][w * 16 + arl][ach]));
        LDSM_X4(al[0], al[1], al[2], al[3], smem_u32(&sAl[p][w * 16 + arl][ach]));
#pragma unroll
        for (int nb = 0; nb < 8; ++nb) {
            uint32_t bh[4];
            LDSM_X4(bh[0], bh[1], bh[2], bh[3],
                    smem_u32(&sBh[p][nb * 16 + bn][bkoff]));
            MMA_BF16(acc[2 * nb],     ah, bh[0], bh[1]);
            MMA_BF16(acc[2 * nb],     al, bh[0], bh[1]);
            MMA_BF16(acc[2 * nb + 1], ah, bh[2], bh[3]);
            MMA_BF16(acc[2 * nb + 1], al, bh[2], bh[3]);
        }
        if (ks + 1 < 32) CVTSTS(p ^ 1);
        __syncthreads();
    }

    const int row0 = r0 + w * 16 + (l >> 2);
    const int col0 = k0 + 2 * (l & 3);
#pragma unroll
    for (int j = 0; j < 16; ++j) {
        *(float2*)&g_dist[(size_t)row0 * KK + col0 + j * 8] =
            make_float2(acc[j][0], acc[j][1]);
        *(float2*)&g_dist[(size_t)(row0 + 8) * KK + col0 + j * 8] =
            make_float2(acc[j][2], acc[j][3]);
    }
}

// ---------------- shared pipelined fp32 GEMM body (gram / u_gemm) ---------
#define SAS 136
#define GEMM_BODY(AROW_EXPR, BBASE, BSTRIDE)                                   \
    const int sm  = tid >> 1;                                                  \
    const int skq = tid & 1;                                                   \
    const int arow = (AROW_EXPR);                                              \
    const float* aptr = Abase + (size_t)arow * DD + 8 * skq;                   \
    const int bk  = tid >> 4;                                                  \
    const int bn4 = (tid & 15) * 4;                                            \
    const float* bbase = (BBASE) + (size_t)bk * (BSTRIDE) + k0;                \
    unsigned long long acc2[8][4];                                             \
    _Pragma("unroll")                                                          \
    for (int i = 0; i < 8; ++i)                                                \
        _Pragma("unroll")                                                      \
        for (int j = 0; j < 4; ++j) acc2[i][j] = 0ull;                         \
    float4 av0, av1, bv0, bv1;                                                 \
    auto LOAD = [&](int cc) {                                                  \
        av0 = *(const float4*)(aptr + cc);                                     \
        av1 = *(const float4*)(aptr + cc + 4);                                 \
        const float* bp = bbase + (size_t)cc * (BSTRIDE);                      \
        bv0 = *(const float4*)(bp + bn4);                                      \
        bv1 = *(const float4*)(bp + 64 + bn4);                                 \
    };                                                                         \
    auto STORE = [&](int p) {                                                  \
        As[p][8 * skq + 0][sm] = av0.x;                                        \
        As[p][8 * skq + 1][sm] = av0.y;                                        \
        As[p][8 * skq + 2][sm] = av0.z;                                        \
        As[p][8 * skq + 3][sm] = av0.w;                                        \
        As[p][8 * skq + 4][sm] = av1.x;                                        \
        As[p][8 * skq + 5][sm] = av1.y;                                        \
        As[p][8 * skq + 6][sm] = av1.z;                                        \
        As[p][8 * skq + 7][sm] = av1.w;                                        \
        *(float4*)&Bs[p][bk][bn4]      = bv0;                                  \
        *(float4*)&Bs[p][bk][64 + bn4] = bv1;                                  \
    };                                                                         \
    LOAD(0); STORE(0);                                                         \
    LOAD(16);                                                                  \
    __syncthreads();                                                           \
    for (int ch = 0; ch < 32; ++ch) {                                          \
        const int p = ch & 1;                                                  \
        if (ch + 1 < 32) STORE(p ^ 1);                                         \
        if (ch + 2 < 32) LOAD((ch + 2) * 16);                                  \
        _Pragma("unroll")                                                      \
        for (int kk = 0; kk < 16; ++kk) {                                      \
            float4 aL = *(const float4*)&As[p][kk][ty * 4];                    \
            float4 aH = *(const float4*)&As[p][kk][64 + ty * 4];               \
            float4 bL = *(const float4*)&Bs[p][kk][tx * 4];                    \
            float4 bH = *(const float4*)&Bs[p][kk][64 + tx * 4];               \
            unsigned long long b2[4], a2;                                      \
            pack2(b2[0], bL.x, bL.y);                                          \
            pack2(b2[1], bL.z, bL.w);                                          \
            pack2(b2[2], bH.x, bH.y);                                          \
            pack2(b2[3], bH.z, bH.w);                                          \
            float arr[8] = {aL.x, aL.y, aL.z, aL.w, aH.x, aH.y, aH.z, aH.w};   \
            _Pragma("unroll")                                                  \
            for (int i = 0; i < 8; ++i) {                                      \
                splat2(a2, arr[i]);                                            \
                _Pragma("unroll")                                              \
                for (int j = 0; j < 4; ++j) ffma2(acc2[i][j], a2, b2[j]);      \
            }                                                                  \
        }                                                                      \
        __syncthreads();                                                       \
    }

// ---------------- Gram GEMM: G = cb · cbT + csq = diag(G) ------------------
__global__ void __launch_bounds__(256, 2) gram_gemm(const float* __restrict__ cb) {
    __shared__ __align__(16) float As[2][16][SAS];
    __shared__ __align__(16) float Bs[2][16][SAS];
    const int tid = threadIdx.x;
    const int tx = tid & 15, ty = tid >> 4;
    const int r0 = blockIdx.x * 128;
    const int k0 = blockIdx.y * 128;
    const float* Abase = cb;
    GEMM_BODY(r0 + (tid >> 1), g_cbT, KK)

#pragma unroll
    for (int i = 0; i < 8; ++i) {
        int m = (i < 4) ? (ty * 4 + i) : (64 + ty * 4 + (i - 4));
        int row = r0 + m;
        float d0, d1, d2, d3;
        unpack2(d0, d1, acc2[i][0]);
        unpack2(d2, d3, acc2[i][1]);
        *(float4*)&g_G[(size_t)row * KK + k0 + tx * 4] = make_float4(d0, d1, d2, d3);
        if (r0 == k0) {
            int c0 = k0 + tx * 4;
            if (row >= c0 && row < c0 + 4) {
                float dd[4] = {d0, d1, d2, d3};
                g_csq[row] = dd[row - c0];
            }
        }
        unpack2(d0, d1, acc2[i][2]);
        unpack2(d2, d3, acc2[i][3]);
        *(float4*)&g_G[(size_t)row * KK + k0 + 64 + tx * 4] = make_float4(d0, d1, d2, d3);
        if (r0 == k0) {
            int c1 = k0 + 64 + tx * 4;
            if (row >= c1 && row < c1 + 4) {
                float dd[4] = {d0, d1, d2, d3};
                g_csq[row] = dd[row - c1];
            }
        }
    }
}

// ---------------- U GEMM: U[tap] = cb · W1_tap^T  (grid 8 x 2 x 3) ---------
__global__ void __launch_bounds__(256, 2) u_gemm(const float* __restrict__ cb) {
    __shared__ __align__(16) float As[2][16][SAS];
    __shared__ __align__(16) float Bs[2][16][SAS];
    const int tid = threadIdx.x;
    const int tx = tid & 15, ty = tid >> 4;
    const int r0 = blockIdx.x * 128;
    const int k0 = blockIdx.y * 128;
    const int tap = blockIdx.z;
    const float* Abase = cb;
    const float* wt3 = g_wT + (size_t)tap * 512 * 256;
    GEMM_BODY(r0 + (tid >> 1), wt3, 256)

#pragma unroll
    for (int i = 0; i < 8; ++i) {
        int m = (i < 4) ? (ty * 4 + i) : (64 + ty * 4 + (i - 4));
        int row = r0 + m;
        float* urow = &g_U[((size_t)tap * KK + row) * 256 + k0];
        float d0, d1, d2, d3;
        unpack2(d0, d1, acc2[i][0]);
        unpack2(d2, d3, acc2[i][1]);
        *(float4*)(urow + tx * 4) = make_float4(d0, d1, d2, d3);
        unpack2(d0, d1, acc2[i][2]);
        unpack2(d2, d3, acc2[i][3]);
        *(float4*)(urow + 64 + tx * 4) = make_float4(d0, d1, d2, d3);
    }
}

// ---------------- init_small ----------------
__global__ void init_small() {
    int tid = threadIdx.x;  // 32
    if (tid < 8) {
        unsigned a, b;
        tf2x32(0u, 42u, 0u, (unsigned)tid, a, b);
        g_fk[2 * tid] = a;
        g_fk[2 * tid + 1] = b;
    }
    if (tid < 2) g_acc[tid] = 0.0f;
    if (tid == 0) {
        float ghi = gumbel_from_bits(0xFFFFFFFFu);
        float glo = gumbel_from_bits(0u);
        g_window = (ghi - glo) + 0.5f;
    }
}

// ---------------- pick: rn2 + all 8 VQ stages per row -> g_sel -------------
__global__ void __launch_bounds__(256) vq_pick() {
    const int bt = blockIdx.x;
    const int tid = threadIdx.x;
    __shared__ unsigned sMaxU;
    __shared__ unsigned long long sBest;
    __shared__ float sDotSel;
    __shared__ int sSel[8];
    __shared__ float red[256];

    if (tid == 0) { sMaxU = 0u; sBest = 0ull; }

    {
        float z0 = g_res[(size_t)bt * DD + tid];
        float z1 = g_res[(size_t)bt * DD + tid + 256];
        red[tid] = z0 * z0 + z1 * z1;
    }

    float d[4], cs[4], s[4];
    const float* drow = &g_dist[(size_t)bt * KK];
#pragma unroll
    for (int j = 0; j < 4; ++j) {
        d[j] = drow[tid + 256 * j];
        cs[j] = g_csq[tid + 256 * j];
        s[j] = fmaf(20.0f, d[j], -10.0f * cs[j]);
    }
    __syncthreads();
    for (int ss = 128; ss > 0; ss >>= 1) {
        if (tid < ss) red[tid] += red[tid + ss];
        __syncthreads();
    }
    const float win = g_window;
    const unsigned btL = (bt < 8192) ? (unsigned)bt : (unsigned)(bt - 8192);
    const bool hi = (bt >= 8192);
    float rn2 = (tid == 0) ? red[0] : 0.0f;
    float commit = 0.0f;

    for (int i = 0; i < 8; ++i) {
        float lm = fmaxf(fmaxf(s[0], s[1]), fmaxf(s[2], s[3]));
#pragma unroll
        for (int off = 16; off > 0; off >>= 1)
            lm = fmaxf(lm, __shfl_xor_sync(0xffffffffu, lm, off));
        if ((tid & 31) == 0) atomicMax(&sMaxU, fmap(lm));
        __syncthreads();
        const float tau = unfmap(sMaxU) - win;

        const unsigned fk0 = g_fk[2 * i], fk1 = g_fk[2 * i + 1];
#pragma unroll
        for (int j = 0; j < 4; ++j) {
            if (s[j] >= tau) {
                unsigned k = (unsigned)(tid + 256 * j);
                unsigned n = btL * 1024u + k;
                unsigned b0, b1;
                tf2x32(fk0, fk1, n, n + HALF_N, b0, b1);
                float g = gumbel_from_bits(hi ? b1 : b0);
                float sc = s[j] + g;
                unsigned long long cand =
                    ((unsigned long long)fmap(sc) << 32) | (unsigned long long)(~k);
                atomicMax(&sBest, cand);
            }
        }
        __syncthreads();
        const unsigned sel = ~(unsigned)(sBest & 0xffffffffull);
        if (tid == (int)(sel & 255u)) sDotSel = d[sel >> 8];
        __syncthreads();
        if (tid == 0) {
            float rn2n = rn2 - 2.0f * sDotSel + g_csq[sel];
            commit += rn2n;
            rn2 = rn2n;
            sSel[i] = (int)sel;
            sMaxU = 0u;
            sBest = 0ull;
        }
        if (i < 7) {
            const float* grow = &g_G[(size_t)sel * KK];
#pragma unroll
            for (int j = 0; j < 4; ++j) {
                d[j] -= grow[tid + 256 * j];
                s[j] = fmaf(20.0f, d[j], -10.0f * cs[j]);
            }
        }
        __syncthreads();
    }

    if (tid < 8) g_sel[bt * 8 + tid] = sSel[tid];
    if (tid == 0) atomicAdd(&g_acc[0], commit);
}

// ---------------- dec1 gather: h1[bt] = gelu(bias + sum U rows) ------------
__global__ void __launch_bounds__(256) dec1_gather(const float* __restrict__ bias) {
    const int bt = blockIdx.x;
    const int c = threadIdx.x;
    __shared__ int sIdx[24];

    if (c < 24) {
        int tap = c >> 3, i = c & 7;
        int t = bt & (TT - 1);
        int st = t + tap - 1;
        int idx = -1;
        if (st >= 0 && st < TT)
            idx = tap * KK + g_sel[(bt + tap - 1) * 8 + i];
        sIdx[c] = idx;
    }
    __syncthreads();

    float acc = bias[c];
#pragma unroll
    for (int j = 0; j < 24; ++j) {
        int idx = sIdx[j];
        if (idx >= 0) acc += g_U[(size_t)idx * 256 + c];
    }
    g_h1[(size_t)bt * 256 + c] = gelu_exact(acc);
}

__global__ void finalize_k(float* __restrict__ out) {
    out[0] = g_acc[1] * (1.0f / 1638400.0f)
           + g_acc[0] * (1.0f / 67108864.0f);
}

// ---------------- streams/events (created once, pre-baseline) --------------
struct SideStream {
    cudaStream_t s;
    cudaEvent_t fork, wtev, join1, join2;
    SideStream() {
        cudaStreamCreateWithFlags(&s, cudaStreamNonBlocking);
        cudaEventCreateWithFlags(&fork, cudaEventDisableTiming);
        cudaEventCreateWithFlags(&wtev, cudaEventDisableTiming);
        cudaEventCreateWithFlags(&join1, cudaEventDisableTiming);
        cudaEventCreateWithFlags(&join2, cudaEventDisableTiming);
    }
};
static SideStream g_ss;

// ---------------- host launcher (graph-capturable, alloc-free) -------------
extern "C" void kernel_launch(void* const* d_in, const int* in_sizes, int n_in,
                              void* d_out, int out_size) {
    const float* x   = (const float*)d_in[0];
    const float* ew1 = (const float*)d_in[1];
    const float* eb1 = (const float*)d_in[2];
    const float* ew2 = (const float*)d_in[3];
    const float* eb2 = (const float*)d_in[4];
    const float* cb  = (const float*)d_in[5];
    const float* dw1 = (const float*)d_in[6];
    const float* db1 = (const float*)d_in[7];
    const float* dw2 = (const float*)d_in[8];
    const float* db2 = (const float*)d_in[9];
    float* out = (float*)d_out;

    float *h1, *res, *wTT, *xpad;
    cudaGetSymbolAddress((void**)&h1,   g_h1);
    cudaGetSymbolAddress((void**)&res,  g_res);
    cudaGetSymbolAddress((void**)&wTT,  g_wTT);
    cudaGetSymbolAddress((void**)&xpad, g_xpad);

    // fork side branch: cbT -> Gram(+csq) -> init_small
    cudaEventRecord(g_ss.fork, 0);
    cudaStreamWaitEvent(g_ss.s, g_ss.fork, 0);
    transpose_cb<<<dim3(KK / 32, DD / 32), dim3(32, 8), 0, g_ss.s>>>(cb);
    gram_gemm<<<dim3(8, 8), 256, 0, g_ss.s>>>(cb);
    init_small<<<1, 32, 0, g_ss.s>>>();
    cudaEventRecord(g_ss.join1, g_ss.s);

    // main branch: weights + x pad -> encoder
    transpose_w_all<<<(WTT_END + 255) / 256, 256>>>(ew1, ew2, dw1, dw2);
    pad_x<<<(BT * 112 + 255) / 256, 256>>>(x);
    cudaEventRecord(g_ss.wtev, 0);

    // side: U = cb · dec_w1^T per tap (needs g_wT) — overlaps encoder convs
    cudaStreamWaitEvent(g_ss.s, g_ss.wtev, 0);
    u_gemm<<<dim3(8, 2, 3), 256, 0, g_ss.s>>>(cb);
    cudaEventRecord(g_ss.join2, g_ss.s);

    conv_mma8<112, 256, 256, 0><<<dim3(128, 2), 256>>>(
        xpad, wTT + WTT_O1, eb1, h1, nullptr);
    conv_mma8<256, 512, 512, 0><<<dim3(128, 4), 256>>>(
        h1, wTT + WTT_O2, eb2, res, nullptr);

    // join: vq needs cbT / G / csq / fk / window
    cudaStreamWaitEvent(0, g_ss.join1, 0);
    vq_gemm_mma<<<dim3(128, 8), 256>>>(res, cb);
    vq_pick<<<BT, 256>>>();

    // decoder: gathered dec1 (needs U), then dec2 mma conv with fused MSE
    cudaStreamWaitEvent(0, g_ss.join2, 0);
    dec1_gather<<<BT, 256>>>(db1);
    conv_mma8<256, 100, 128, 1><<<dim3(128, 1), 256>>>(
        h1, wTT + WTT_O4, db2, nullptr, x);

    finalize_k<<<1, 1>>>(out);
}